// round 1
// baseline (speedup 1.0000x reference)
#include <cuda_runtime.h>

#define D_MODEL 1024
#define N_HEADS 16
#define HEAD_DIM 64
#define SEQ 2048
#define BATCH 2

// Scratch (allocation-free rule: __device__ globals)
__device__ float g_qkv[BATCH * SEQ * 3 * D_MODEL];  // [B,S,3D]
__device__ float g_att[BATCH * SEQ * D_MODEL];      // [B,S,D] (head-merged attention out)

// ---------------------------------------------------------------------------
// SGEMM + bias: C[M,N] = A[M,K] @ B[K,N] + bias[N]
// 128x128 block tile, BK=8, 256 threads, 8x8 per thread.
// ---------------------------------------------------------------------------
#define BM 128
#define BN 128
#define BKg 8

__global__ __launch_bounds__(256) void sgemm_bias_kernel(
    const float* __restrict__ A, const float* __restrict__ B,
    const float* __restrict__ bias, float* __restrict__ C,
    int M, int N, int K)
{
    __shared__ float As[BKg][BM];   // transposed: [k][m]
    __shared__ float Bs[BKg][BN];   // [k][n]

    const int tid = threadIdx.x;
    const int tx = tid & 15;        // 0..15  (N direction)
    const int ty = tid >> 4;        // 0..15  (M direction)
    const int row0 = blockIdx.y * BM;
    const int col0 = blockIdx.x * BN;

    // A tile load: 128 rows x 8 k = 256 float4; thread -> (row=tid/2, k4=tid%2)
    const int ar = tid >> 1;
    const int ak = (tid & 1) * 4;
    // B tile load: 8 rows x 128 cols = 256 float4; thread -> (k=tid/32, col=(tid%32)*4)
    const int br = tid >> 5;
    const int bc = (tid & 31) * 4;

    const float* Ap = A + (size_t)(row0 + ar) * K + ak;
    const float* Bp = B + (size_t)br * N + col0 + bc;

    float acc[8][8];
#pragma unroll
    for (int i = 0; i < 8; i++)
#pragma unroll
        for (int j = 0; j < 8; j++) acc[i][j] = 0.0f;

    for (int k0 = 0; k0 < K; k0 += BKg) {
        float4 a4 = *(const float4*)Ap;
        float4 b4 = *(const float4*)Bp;
        As[ak + 0][ar] = a4.x;
        As[ak + 1][ar] = a4.y;
        As[ak + 2][ar] = a4.z;
        As[ak + 3][ar] = a4.w;
        *(float4*)&Bs[br][bc] = b4;
        __syncthreads();

#pragma unroll
        for (int kk = 0; kk < BKg; kk++) {
            float4 a0 = *(const float4*)&As[kk][ty * 8];
            float4 a1 = *(const float4*)&As[kk][ty * 8 + 4];
            float4 b0 = *(const float4*)&Bs[kk][tx * 8];
            float4 b1 = *(const float4*)&Bs[kk][tx * 8 + 4];
            float av[8] = {a0.x, a0.y, a0.z, a0.w, a1.x, a1.y, a1.z, a1.w};
            float bv[8] = {b0.x, b0.y, b0.z, b0.w, b1.x, b1.y, b1.z, b1.w};
#pragma unroll
            for (int i = 0; i < 8; i++)
#pragma unroll
                for (int j = 0; j < 8; j++)
                    acc[i][j] = fmaf(av[i], bv[j], acc[i][j]);
        }
        __syncthreads();

        Ap += BKg;
        Bp += (size_t)BKg * N;
    }

    // Epilogue with bias
    const float* bptr = bias + col0 + tx * 8;
    float4 bb0 = *(const float4*)bptr;
    float4 bb1 = *(const float4*)(bptr + 4);
    float bb[8] = {bb0.x, bb0.y, bb0.z, bb0.w, bb1.x, bb1.y, bb1.z, bb1.w};
#pragma unroll
    for (int i = 0; i < 8; i++) {
        float* Cp = C + (size_t)(row0 + ty * 8 + i) * N + col0 + tx * 8;
        float4 c0 = make_float4(acc[i][0] + bb[0], acc[i][1] + bb[1],
                                acc[i][2] + bb[2], acc[i][3] + bb[3]);
        float4 c1 = make_float4(acc[i][4] + bb[4], acc[i][5] + bb[5],
                                acc[i][6] + bb[6], acc[i][7] + bb[7]);
        *(float4*)Cp = c0;
        *(float4*)(Cp + 4) = c1;
    }
}

// ---------------------------------------------------------------------------
// Flash attention (fp32, causal, online softmax).
// Block = (qtile, head, batch). 64 query rows per block, 64 keys per iter.
// 256 threads as 16x16; each thread owns a 4x4 patch of the 64x64 score tile
// and a 4x4 patch of the 64-wide output accumulator.
// Q/K stored d-major in smem ([d][row]) with a 4-float XOR swizzle:
//   phys_row = row ^ (((d>>2)&7)<<2)
// which keeps float4 reads aligned & conflict-free and caps transposed-store
// conflicts at ~2-way. V and P are row-major (naturally conflict-free).
// ---------------------------------------------------------------------------
__global__ __launch_bounds__(256) void flash_kernel(
    const float* __restrict__ qkv, float* __restrict__ att)
{
    extern __shared__ float sm[];
    float* q_t = sm;             // 64*64 (d-major, swizzled, pre-scaled by 1/8)
    float* k_t = sm + 4096;      // 64*64 (d-major, swizzled)
    float* v_s = sm + 8192;      // 64*64 row-major [krow][d]
    float* p_s = sm + 12288;     // 64*64 row-major [qrow][kcol]
    float* red = sm + 16384;     // 64*16 reduction buffer

    const int tid = threadIdx.x;
    const int tx = tid & 15;
    const int ty = tid >> 4;
    const int qt = blockIdx.x;
    const int h  = blockIdx.y;
    const int b  = blockIdx.z;
    const int q0 = qt * 64;

    const size_t row_stride = 3 * D_MODEL;  // 3072
    const float* qbase = qkv + (size_t)b * SEQ * row_stride + h * HEAD_DIM;
    const float* kbase = qbase + D_MODEL;
    const float* vbase = qbase + 2 * D_MODEL;

    const int c4 = tid & 15;   // float4 column group within 64-wide head dim
    const int rb = tid >> 4;   // row base (iterate +16)
    const int sw = (c4 & 7) << 2;

    // ---- Load Q (transposed + swizzled + pre-scaled) ----
#pragma unroll
    for (int it = 0; it < 4; it++) {
        int rr = rb + it * 16;
        float4 v = *(const float4*)(qbase + (size_t)(q0 + rr) * row_stride + c4 * 4);
        int pr = rr ^ sw;
        q_t[(c4 * 4 + 0) * 64 + pr] = v.x * 0.125f;
        q_t[(c4 * 4 + 1) * 64 + pr] = v.y * 0.125f;
        q_t[(c4 * 4 + 2) * 64 + pr] = v.z * 0.125f;
        q_t[(c4 * 4 + 3) * 64 + pr] = v.w * 0.125f;
    }

    float m[4], l[4], o[4][4];
#pragma unroll
    for (int i = 0; i < 4; i++) {
        m[i] = -1e30f;
        l[i] = 0.0f;
#pragma unroll
        for (int j = 0; j < 4; j++) o[i][j] = 0.0f;
    }

    for (int t = 0; t <= qt; t++) {
        const int k0 = t * 64;

        // ---- Load K (transposed+swizzled) and V (row-major) ----
#pragma unroll
        for (int it = 0; it < 4; it++) {
            int rr = rb + it * 16;
            float4 kv4 = *(const float4*)(kbase + (size_t)(k0 + rr) * row_stride + c4 * 4);
            int pr = rr ^ sw;
            k_t[(c4 * 4 + 0) * 64 + pr] = kv4.x;
            k_t[(c4 * 4 + 1) * 64 + pr] = kv4.y;
            k_t[(c4 * 4 + 2) * 64 + pr] = kv4.z;
            k_t[(c4 * 4 + 3) * 64 + pr] = kv4.w;
            float4 vv4 = *(const float4*)(vbase + (size_t)(k0 + rr) * row_stride + c4 * 4);
            *(float4*)&v_s[rr * 64 + c4 * 4] = vv4;
        }
        __syncthreads();

        // ---- S = (Q*scale) @ K^T ----
        float s[4][4];
#pragma unroll
        for (int i = 0; i < 4; i++)
#pragma unroll
            for (int j = 0; j < 4; j++) s[i][j] = 0.0f;

#pragma unroll 16
        for (int d = 0; d < 64; d++) {
            int dsw = ((d >> 2) & 7) << 2;
            float4 qa = *(const float4*)&q_t[d * 64 + ((ty * 4) ^ dsw)];
            float4 ka = *(const float4*)&k_t[d * 64 + ((tx * 4) ^ dsw)];
            float qv[4] = {qa.x, qa.y, qa.z, qa.w};
            float kv[4] = {ka.x, ka.y, ka.z, ka.w};
#pragma unroll
            for (int i = 0; i < 4; i++)
#pragma unroll
                for (int j = 0; j < 4; j++)
                    s[i][j] = fmaf(qv[i], kv[j], s[i][j]);
        }

        // ---- Causal mask (only the diagonal tile needs it) ----
        if (t == qt) {
#pragma unroll
            for (int i = 0; i < 4; i++)
#pragma unroll
                for (int j = 0; j < 4; j++)
                    if (k0 + tx * 4 + j > q0 + ty * 4 + i) s[i][j] = -1e30f;
        }

        // ---- Row max partials ----
#pragma unroll
        for (int i = 0; i < 4; i++) {
            float mx = fmaxf(fmaxf(s[i][0], s[i][1]), fmaxf(s[i][2], s[i][3]));
            red[(ty * 4 + i) * 16 + tx] = mx;
        }
        __syncthreads();

        float mnew[4], p[4][4];
#pragma unroll
        for (int i = 0; i < 4; i++) {
            int r = ty * 4 + i;
            float mx = -1e30f;
#pragma unroll
            for (int tt = 0; tt < 16; tt++) mx = fmaxf(mx, red[r * 16 + tt]);
            mnew[i] = fmaxf(m[i], mx);
#pragma unroll
            for (int j = 0; j < 4; j++) p[i][j] = __expf(s[i][j] - mnew[i]);
        }
        __syncthreads();  // everyone done reading max partials

        // ---- Row sum partials + stage P to smem ----
#pragma unroll
        for (int i = 0; i < 4; i++) {
            red[(ty * 4 + i) * 16 + tx] = p[i][0] + p[i][1] + p[i][2] + p[i][3];
            *(float4*)&p_s[(ty * 4 + i) * 64 + tx * 4] =
                make_float4(p[i][0], p[i][1], p[i][2], p[i][3]);
        }
        __syncthreads();

        // ---- Online softmax state update + rescale O ----
#pragma unroll
        for (int i = 0; i < 4; i++) {
            int r = ty * 4 + i;
            float rs = 0.0f;
#pragma unroll
            for (int tt = 0; tt < 16; tt++) rs += red[r * 16 + tt];
            float alpha = __expf(m[i] - mnew[i]);
            l[i] = l[i] * alpha + rs;
            m[i] = mnew[i];
#pragma unroll
            for (int j = 0; j < 4; j++) o[i][j] *= alpha;
        }

        // ---- O += P @ V ----
#pragma unroll 8
        for (int kk4 = 0; kk4 < 64; kk4 += 4) {
            float pr4[4][4];
#pragma unroll
            for (int i = 0; i < 4; i++) {
                float4 pp = *(const float4*)&p_s[(ty * 4 + i) * 64 + kk4];
                pr4[i][0] = pp.x; pr4[i][1] = pp.y; pr4[i][2] = pp.z; pr4[i][3] = pp.w;
            }
#pragma unroll
            for (int kki = 0; kki < 4; kki++) {
                float4 vv = *(const float4*)&v_s[(kk4 + kki) * 64 + tx * 4];
                float vr[4] = {vv.x, vv.y, vv.z, vv.w};
#pragma unroll
                for (int i = 0; i < 4; i++)
#pragma unroll
                    for (int j = 0; j < 4; j++)
                        o[i][j] = fmaf(pr4[i][kki], vr[j], o[i][j]);
            }
        }
        __syncthreads();  // protect k_t/v_s/p_s before next tile's loads
    }

    // ---- Normalize & write [B,S,H*Hd] ----
#pragma unroll
    for (int i = 0; i < 4; i++) {
        float inv = 1.0f / l[i];
        int qg = q0 + ty * 4 + i;
        float4 ov = make_float4(o[i][0] * inv, o[i][1] * inv,
                                o[i][2] * inv, o[i][3] * inv);
        *(float4*)&att[((size_t)(b * SEQ + qg)) * D_MODEL + h * HEAD_DIM + tx * 4] = ov;
    }
}

// ---------------------------------------------------------------------------
extern "C" void kernel_launch(void* const* d_in, const int* in_sizes, int n_in,
                              void* d_out, int out_size)
{
    const float* x      = (const float*)d_in[0];  // [2,2048,1024]
    const float* w_qkv  = (const float*)d_in[1];  // [1024,3072]
    const float* b_qkv  = (const float*)d_in[2];  // [3072]
    const float* w_proj = (const float*)d_in[3];  // [1024,1024]
    const float* b_proj = (const float*)d_in[4];  // [1024]
    float* out = (float*)d_out;                   // [2,2048,1024]

    float* qkv = nullptr;
    float* att = nullptr;
    cudaGetSymbolAddress((void**)&qkv, g_qkv);
    cudaGetSymbolAddress((void**)&att, g_att);

    const int M = BATCH * SEQ;          // 4096
    const int smem_bytes = (4 * 64 * 64 + 64 * 16) * sizeof(float);  // 69632
    cudaFuncSetAttribute(flash_kernel,
                         cudaFuncAttributeMaxDynamicSharedMemorySize, smem_bytes);

    // 1) QKV GEMM + bias: [4096,1024] @ [1024,3072]
    sgemm_bias_kernel<<<dim3(3 * D_MODEL / BN, M / BM), 256>>>(
        x, w_qkv, b_qkv, qkv, M, 3 * D_MODEL, D_MODEL);

    // 2) Causal flash attention over 64-row query tiles
    flash_kernel<<<dim3(SEQ / 64, N_HEADS, BATCH), 256, smem_bytes>>>(qkv, att);

    // 3) Output projection + bias: [4096,1024] @ [1024,1024]
    sgemm_bias_kernel<<<dim3(D_MODEL / BN, M / BM), 256>>>(
        att, w_proj, b_proj, out, M, D_MODEL, D_MODEL);
}

// round 3
// speedup vs baseline: 1.0759x; 1.0759x over previous
#include <cuda_runtime.h>
#include <cstdint>

#define D_MODEL 1024
#define N_HEADS 16
#define HEAD_DIM 64
#define SEQ 2048
#define BATCH 2
#define GK 1024

// Scratch (allocation-free rule: __device__ globals)
__device__ float g_qkv[BATCH * SEQ * 3 * D_MODEL];   // [B,S,3D]
__device__ float g_att[BATCH * SEQ * D_MODEL];       // [B,S,D]
__device__ float g_wqkv_t[3 * D_MODEL * D_MODEL];    // [3072][1024]  (W^T)
__device__ float g_wproj_t[D_MODEL * D_MODEL];       // [1024][1024]  (W^T)

__device__ __forceinline__ float tf32_rna(float x) {
    uint32_t r;
    asm("cvt.rna.tf32.f32 %0, %1;" : "=r"(r) : "f"(x));
    return __uint_as_float(r);
}

__device__ __forceinline__ void mma8(float* d, const uint4& a, const uint2& b) {
    asm volatile(
        "mma.sync.aligned.m16n8k8.row.col.f32.tf32.tf32.f32 "
        "{%0,%1,%2,%3}, {%4,%5,%6,%7}, {%8,%9}, {%0,%1,%2,%3};"
        : "+f"(d[0]), "+f"(d[1]), "+f"(d[2]), "+f"(d[3])
        : "r"(a.x), "r"(a.y), "r"(a.z), "r"(a.w), "r"(b.x), "r"(b.y));
}

// ---------------------------------------------------------------------------
// Weight transpose: out[c][r] = in[r][c]
// ---------------------------------------------------------------------------
__global__ __launch_bounds__(256) void transpose_k(const float* __restrict__ in,
                                                   float* __restrict__ out,
                                                   int R, int C) {
    __shared__ float t[32][33];
    int c0 = blockIdx.x * 32, r0 = blockIdx.y * 32;
    int x = threadIdx.x, y = threadIdx.y;
#pragma unroll
    for (int i = 0; i < 32; i += 8)
        t[y + i][x] = in[(size_t)(r0 + y + i) * C + c0 + x];
    __syncthreads();
#pragma unroll
    for (int i = 0; i < 32; i += 8)
        out[(size_t)(c0 + y + i) * R + r0 + x] = t[x][y + i];
}

// ---------------------------------------------------------------------------
// mma.sync tf32 GEMM (3xTF32 split): C[M,N] = A[M,K] @ Bt[N,K]^T + bias[N]
// CTA tile 128x128, K-chunk 32, double-buffered smem, 256 threads (8 warps),
// warp tile 64x32 (4x4 grid of m16n8k8).
// Smem layout (per stage, float offsets):
//   Ah @ 0      : [4 ks][8 mtile][32 lane][4]  = 4096 floats
//   Al @ 4096   : same
//   Bh @ 8192   : [4 ks][16 ntile][32 lane][2] = 2048 floats
//   Bl @ 12288  : ... wait Bh is [4][16][32][2] = 4096 floats
// (see offsets in code: Ah 0, Al 4096, Bh 8192, Bl 12288; stage stride 16384)
// All STS/LDS are lane-consecutive vectors => conflict-free.
// ---------------------------------------------------------------------------
#define STG_STRIDE 16384
#define GEMM_SMEM (2 * STG_STRIDE * 4)

__global__ __launch_bounds__(256, 1)
void tc_gemm(const float* __restrict__ A, const float* __restrict__ Bt,
             const float* __restrict__ bias, float* __restrict__ C, int N)
{
    extern __shared__ float smf[];
    const int tid = threadIdx.x;
    const int lane = tid & 31;
    const int wid = tid >> 5;
    const int wm = wid >> 2;       // 0..1 (64-row half)
    const int wn = wid & 3;        // 0..3 (32-col quarter)
    const int row0 = blockIdx.y * 128;
    const int col0 = blockIdx.x * 128;

    // ---- loader descriptors ----
    // A hi/lo fragments: f in [0,1024): ks=f>>8, mtile=(f>>5)&7, lane=f&31
    const float* aptr[4];
    uint32_t asidx[4];
#pragma unroll
    for (int q = 0; q < 4; q++) {
        int f = tid + q * 256;
        int ks = f >> 8, mt = (f >> 5) & 7, ln = f & 31;
        int r = ln >> 2, kq = ln & 3;
        aptr[q] = A + (size_t)(row0 + mt * 16 + r) * GK + ks * 8 + kq;
        asidx[q] = (uint32_t)f * 4;
    }
    // B fragments: g in [0,2048): ks=g>>9, ntile=(g>>5)&15, lane=g&31
    const float* bptr[8];
    uint32_t bsidx[8];
#pragma unroll
    for (int q = 0; q < 8; q++) {
        int g = tid + q * 256;
        int ks = g >> 9, nt = (g >> 5) & 15, ln = g & 31;
        bptr[q] = Bt + (size_t)(col0 + nt * 8 + (ln >> 2)) * GK + ks * 8 + (ln & 3);
        bsidx[q] = (uint32_t)g * 2;
    }

    float acc[4][4][4];
#pragma unroll
    for (int i = 0; i < 4; i++)
#pragma unroll
        for (int j = 0; j < 4; j++)
#pragma unroll
            for (int c = 0; c < 4; c++) acc[i][j][c] = 0.0f;

    float av[4][4], bv[8][2];

    auto ldg = [&](int c) {
        const int o = c * 32;
#pragma unroll
        for (int q = 0; q < 4; q++) {
            av[q][0] = __ldg(aptr[q] + o);
            av[q][1] = __ldg(aptr[q] + o + 8 * GK);
            av[q][2] = __ldg(aptr[q] + o + 4);
            av[q][3] = __ldg(aptr[q] + o + 8 * GK + 4);
        }
#pragma unroll
        for (int q = 0; q < 8; q++) {
            bv[q][0] = __ldg(bptr[q] + o);
            bv[q][1] = __ldg(bptr[q] + o + 4);
        }
    };

    auto sts = [&](int st) {
        float* base = smf + st * STG_STRIDE;
#pragma unroll
        for (int q = 0; q < 4; q++) {
            float4 h, l;
            h.x = tf32_rna(av[q][0]); l.x = tf32_rna(av[q][0] - h.x);
            h.y = tf32_rna(av[q][1]); l.y = tf32_rna(av[q][1] - h.y);
            h.z = tf32_rna(av[q][2]); l.z = tf32_rna(av[q][2] - h.z);
            h.w = tf32_rna(av[q][3]); l.w = tf32_rna(av[q][3] - h.w);
            *(float4*)(base + asidx[q]) = h;
            *(float4*)(base + 4096 + asidx[q]) = l;
        }
#pragma unroll
        for (int q = 0; q < 8; q++) {
            float2 h, l;
            h.x = tf32_rna(bv[q][0]); l.x = tf32_rna(bv[q][0] - h.x);
            h.y = tf32_rna(bv[q][1]); l.y = tf32_rna(bv[q][1] - h.y);
            *(float2*)(base + 8192 + bsidx[q]) = h;
            *(float2*)(base + 12288 + bsidx[q]) = l;
        }
    };

    ldg(0);
    sts(0);
    __syncthreads();

    for (int c = 0; c < GK / 32; c++) {
        const int st = c & 1;
        if (c + 1 < GK / 32) ldg(c + 1);

        const float* base = smf + st * STG_STRIDE;
#pragma unroll
        for (int ks = 0; ks < 4; ks++) {
            uint4 AH[4], AL[4];
            uint2 BH[4], BL[4];
#pragma unroll
            for (int mi = 0; mi < 4; mi++) {
                uint32_t idx = ((ks * 8 + wm * 4 + mi) * 32 + lane) * 4;
                AH[mi] = *(const uint4*)(base + idx);
                AL[mi] = *(const uint4*)(base + 4096 + idx);
            }
#pragma unroll
            for (int ni = 0; ni < 4; ni++) {
                uint32_t idx = ((ks * 16 + wn * 4 + ni) * 32 + lane) * 2;
                BH[ni] = *(const uint2*)(base + 8192 + idx);
                BL[ni] = *(const uint2*)(base + 12288 + idx);
            }
            // pass 1: hi*hi ; pass 2: hi*lo ; pass 3: lo*hi  (dep distance 16)
#pragma unroll
            for (int mi = 0; mi < 4; mi++)
#pragma unroll
                for (int ni = 0; ni < 4; ni++)
                    mma8(acc[mi][ni], AH[mi], BH[ni]);
#pragma unroll
            for (int mi = 0; mi < 4; mi++)
#pragma unroll
                for (int ni = 0; ni < 4; ni++)
                    mma8(acc[mi][ni], AH[mi], BL[ni]);
#pragma unroll
            for (int mi = 0; mi < 4; mi++)
#pragma unroll
                for (int ni = 0; ni < 4; ni++)
                    mma8(acc[mi][ni], AL[mi], BH[ni]);
        }

        if (c + 1 < GK / 32) sts((c + 1) & 1);
        __syncthreads();
    }

    // ---- epilogue: acc -> C with bias ----
#pragma unroll
    for (int mi = 0; mi < 4; mi++) {
        const int m = row0 + wm * 64 + mi * 16 + (lane >> 2);
#pragma unroll
        for (int ni = 0; ni < 4; ni++) {
            const int n = col0 + wn * 32 + ni * 8 + (lane & 3) * 2;
            float2 bb = *(const float2*)(bias + n);
            float2 o0 = make_float2(acc[mi][ni][0] + bb.x, acc[mi][ni][1] + bb.y);
            float2 o1 = make_float2(acc[mi][ni][2] + bb.x, acc[mi][ni][3] + bb.y);
            *(float2*)(C + (size_t)m * N + n) = o0;
            *(float2*)(C + (size_t)(m + 8) * N + n) = o1;
        }
    }
}

// ---------------------------------------------------------------------------
// Flash attention (fp32, causal, online softmax) — unchanged from R1.
// ---------------------------------------------------------------------------
__global__ __launch_bounds__(256) void flash_kernel(
    const float* __restrict__ qkv, float* __restrict__ att)
{
    extern __shared__ float smf[];
    float* q_t = smf;
    float* k_t = smf + 4096;
    float* v_s = smf + 8192;
    float* p_s = smf + 12288;
    float* red = smf + 16384;

    const int tid = threadIdx.x;
    const int tx = tid & 15;
    const int ty = tid >> 4;
    const int qt = blockIdx.x;
    const int h  = blockIdx.y;
    const int b  = blockIdx.z;
    const int q0 = qt * 64;

    const size_t row_stride = 3 * D_MODEL;
    const float* qbase = qkv + (size_t)b * SEQ * row_stride + h * HEAD_DIM;
    const float* kbase = qbase + D_MODEL;
    const float* vbase = qbase + 2 * D_MODEL;

    const int c4 = tid & 15;
    const int rb = tid >> 4;
    const int sw = (c4 & 7) << 2;

#pragma unroll
    for (int it = 0; it < 4; it++) {
        int rr = rb + it * 16;
        float4 v = *(const float4*)(qbase + (size_t)(q0 + rr) * row_stride + c4 * 4);
        int pr = rr ^ sw;
        q_t[(c4 * 4 + 0) * 64 + pr] = v.x * 0.125f;
        q_t[(c4 * 4 + 1) * 64 + pr] = v.y * 0.125f;
        q_t[(c4 * 4 + 2) * 64 + pr] = v.z * 0.125f;
        q_t[(c4 * 4 + 3) * 64 + pr] = v.w * 0.125f;
    }

    float m[4], l[4], o[4][4];
#pragma unroll
    for (int i = 0; i < 4; i++) {
        m[i] = -1e30f;
        l[i] = 0.0f;
#pragma unroll
        for (int j = 0; j < 4; j++) o[i][j] = 0.0f;
    }

    for (int t = 0; t <= qt; t++) {
        const int k0 = t * 64;

#pragma unroll
        for (int it = 0; it < 4; it++) {
            int rr = rb + it * 16;
            float4 kv4 = *(const float4*)(kbase + (size_t)(k0 + rr) * row_stride + c4 * 4);
            int pr = rr ^ sw;
            k_t[(c4 * 4 + 0) * 64 + pr] = kv4.x;
            k_t[(c4 * 4 + 1) * 64 + pr] = kv4.y;
            k_t[(c4 * 4 + 2) * 64 + pr] = kv4.z;
            k_t[(c4 * 4 + 3) * 64 + pr] = kv4.w;
            float4 vv4 = *(const float4*)(vbase + (size_t)(k0 + rr) * row_stride + c4 * 4);
            *(float4*)&v_s[rr * 64 + c4 * 4] = vv4;
        }
        __syncthreads();

        float s[4][4];
#pragma unroll
        for (int i = 0; i < 4; i++)
#pragma unroll
            for (int j = 0; j < 4; j++) s[i][j] = 0.0f;

#pragma unroll 16
        for (int d = 0; d < 64; d++) {
            int dsw = ((d >> 2) & 7) << 2;
            float4 qa = *(const float4*)&q_t[d * 64 + ((ty * 4) ^ dsw)];
            float4 ka = *(const float4*)&k_t[d * 64 + ((tx * 4) ^ dsw)];
            float qv[4] = {qa.x, qa.y, qa.z, qa.w};
            float kv[4] = {ka.x, ka.y, ka.z, ka.w};
#pragma unroll
            for (int i = 0; i < 4; i++)
#pragma unroll
                for (int j = 0; j < 4; j++)
                    s[i][j] = fmaf(qv[i], kv[j], s[i][j]);
        }

        if (t == qt) {
#pragma unroll
            for (int i = 0; i < 4; i++)
#pragma unroll
                for (int j = 0; j < 4; j++)
                    if (k0 + tx * 4 + j > q0 + ty * 4 + i) s[i][j] = -1e30f;
        }

#pragma unroll
        for (int i = 0; i < 4; i++) {
            float mx = fmaxf(fmaxf(s[i][0], s[i][1]), fmaxf(s[i][2], s[i][3]));
            red[(ty * 4 + i) * 16 + tx] = mx;
        }
        __syncthreads();

        float mnew[4], p[4][4];
#pragma unroll
        for (int i = 0; i < 4; i++) {
            int rr = ty * 4 + i;
            float mx = -1e30f;
#pragma unroll
            for (int tt = 0; tt < 16; tt++) mx = fmaxf(mx, red[rr * 16 + tt]);
            mnew[i] = fmaxf(m[i], mx);
#pragma unroll
            for (int j = 0; j < 4; j++) p[i][j] = __expf(s[i][j] - mnew[i]);
        }
        __syncthreads();

#pragma unroll
        for (int i = 0; i < 4; i++) {
            red[(ty * 4 + i) * 16 + tx] = p[i][0] + p[i][1] + p[i][2] + p[i][3];
            *(float4*)&p_s[(ty * 4 + i) * 64 + tx * 4] =
                make_float4(p[i][0], p[i][1], p[i][2], p[i][3]);
        }
        __syncthreads();

#pragma unroll
        for (int i = 0; i < 4; i++) {
            int rr = ty * 4 + i;
            float rs = 0.0f;
#pragma unroll
            for (int tt = 0; tt < 16; tt++) rs += red[rr * 16 + tt];
            float alpha = __expf(m[i] - mnew[i]);
            l[i] = l[i] * alpha + rs;
            m[i] = mnew[i];
#pragma unroll
            for (int j = 0; j < 4; j++) o[i][j] *= alpha;
        }

#pragma unroll 8
        for (int kk4 = 0; kk4 < 64; kk4 += 4) {
            float pr4[4][4];
#pragma unroll
            for (int i = 0; i < 4; i++) {
                float4 pp = *(const float4*)&p_s[(ty * 4 + i) * 64 + kk4];
                pr4[i][0] = pp.x; pr4[i][1] = pp.y; pr4[i][2] = pp.z; pr4[i][3] = pp.w;
            }
#pragma unroll
            for (int kki = 0; kki < 4; kki++) {
                float4 vv = *(const float4*)&v_s[(kk4 + kki) * 64 + tx * 4];
                float vr[4] = {vv.x, vv.y, vv.z, vv.w};
#pragma unroll
                for (int i = 0; i < 4; i++)
#pragma unroll
                    for (int j = 0; j < 4; j++)
                        o[i][j] = fmaf(pr4[i][kki], vr[j], o[i][j]);
            }
        }
        __syncthreads();
    }

#pragma unroll
    for (int i = 0; i < 4; i++) {
        float inv = 1.0f / l[i];
        int qg = q0 + ty * 4 + i;
        float4 ov = make_float4(o[i][0] * inv, o[i][1] * inv,
                                o[i][2] * inv, o[i][3] * inv);
        *(float4*)&att[((size_t)(b * SEQ + qg)) * D_MODEL + h * HEAD_DIM + tx * 4] = ov;
    }
}

// ---------------------------------------------------------------------------
extern "C" void kernel_launch(void* const* d_in, const int* in_sizes, int n_in,
                              void* d_out, int out_size)
{
    const float* x      = (const float*)d_in[0];
    const float* w_qkv  = (const float*)d_in[1];
    const float* b_qkv  = (const float*)d_in[2];
    const float* w_proj = (const float*)d_in[3];
    const float* b_proj = (const float*)d_in[4];
    float* out = (float*)d_out;

    float *qkv = nullptr, *att = nullptr, *wqkvT = nullptr, *wprojT = nullptr;
    cudaGetSymbolAddress((void**)&qkv, g_qkv);
    cudaGetSymbolAddress((void**)&att, g_att);
    cudaGetSymbolAddress((void**)&wqkvT, g_wqkv_t);
    cudaGetSymbolAddress((void**)&wprojT, g_wproj_t);

    const int M = BATCH * SEQ;  // 4096
    const int flash_smem = (4 * 64 * 64 + 64 * 16) * sizeof(float);
    cudaFuncSetAttribute(flash_kernel,
                         cudaFuncAttributeMaxDynamicSharedMemorySize, flash_smem);
    cudaFuncSetAttribute(tc_gemm,
                         cudaFuncAttributeMaxDynamicSharedMemorySize, GEMM_SMEM);

    // 0) weight transposes (W^T: [N][K], K contiguous)
    transpose_k<<<dim3(3 * D_MODEL / 32, D_MODEL / 32), dim3(32, 8)>>>(
        w_qkv, wqkvT, D_MODEL, 3 * D_MODEL);
    transpose_k<<<dim3(D_MODEL / 32, D_MODEL / 32), dim3(32, 8)>>>(
        w_proj, wprojT, D_MODEL, D_MODEL);

    // 1) QKV GEMM (mma.sync tf32 3x-split): [4096,1024] @ [1024,3072]
    tc_gemm<<<dim3(3 * D_MODEL / 128, M / 128), 256, GEMM_SMEM>>>(
        x, wqkvT, b_qkv, qkv, 3 * D_MODEL);

    // 2) Causal flash attention
    flash_kernel<<<dim3(SEQ / 64, N_HEADS, BATCH), 256, flash_smem>>>(qkv, att);

    // 3) Output projection: [4096,1024] @ [1024,1024]
    tc_gemm<<<dim3(D_MODEL / 128, M / 128), 256, GEMM_SMEM>>>(
        att, wprojT, b_proj, out, D_MODEL);
}

// round 4
// speedup vs baseline: 1.4220x; 1.3217x over previous
#include <cuda_runtime.h>
#include <cuda_bf16.h>
#include <cstdint>

#define D_MODEL 1024
#define N_HEADS 16
#define HEAD_DIM 64
#define SEQ 2048
#define BATCH 2
#define GK 1024

// Scratch (allocation-free rule: __device__ globals)
__device__ float g_qkv[BATCH * SEQ * 3 * D_MODEL];   // [B,S,3D]
__device__ float g_att[BATCH * SEQ * D_MODEL];       // [B,S,D]
__device__ float g_wqkv_t[3 * D_MODEL * D_MODEL];    // [3072][1024]  (W^T)
__device__ float g_wproj_t[D_MODEL * D_MODEL];       // [1024][1024]  (W^T)

__device__ __forceinline__ uint32_t pack_bf16_hi(float x, float y,
                                                 float& rx, float& ry) {
    __nv_bfloat16 hx = __float2bfloat16(x);
    __nv_bfloat16 hy = __float2bfloat16(y);
    rx = x - __bfloat162float(hx);
    ry = y - __bfloat162float(hy);
    __nv_bfloat162 p = __halves2bfloat162(hx, hy);   // lo = x, hi = y
    return *reinterpret_cast<uint32_t*>(&p);
}
__device__ __forceinline__ uint32_t pack_bf16(float x, float y) {
    __nv_bfloat162 p = __floats2bfloat162_rn(x, y);
    return *reinterpret_cast<uint32_t*>(&p);
}

__device__ __forceinline__ void mma16(float* d, const uint4& a, const uint2& b) {
    asm volatile(
        "mma.sync.aligned.m16n8k16.row.col.f32.bf16.bf16.f32 "
        "{%0,%1,%2,%3}, {%4,%5,%6,%7}, {%8,%9}, {%0,%1,%2,%3};"
        : "+f"(d[0]), "+f"(d[1]), "+f"(d[2]), "+f"(d[3])
        : "r"(a.x), "r"(a.y), "r"(a.z), "r"(a.w), "r"(b.x), "r"(b.y));
}

// ---------------------------------------------------------------------------
// Weight transpose: out[c][r] = in[r][c]
// ---------------------------------------------------------------------------
__global__ __launch_bounds__(256) void transpose_k(const float* __restrict__ in,
                                                   float* __restrict__ out,
                                                   int R, int C) {
    __shared__ float t[32][33];
    int c0 = blockIdx.x * 32, r0 = blockIdx.y * 32;
    int x = threadIdx.x, y = threadIdx.y;
#pragma unroll
    for (int i = 0; i < 32; i += 8)
        t[y + i][x] = in[(size_t)(r0 + y + i) * C + c0 + x];
    __syncthreads();
#pragma unroll
    for (int i = 0; i < 32; i += 8)
        out[(size_t)(c0 + y + i) * R + r0 + x] = t[x][y + i];
}

// ---------------------------------------------------------------------------
// mma.sync bf16 GEMM (3x bf16 split): C[M,N] = A[M,K] @ Bt[N,K]^T + bias[N]
// CTA tile 128x128, K-chunk 32, double-buffered smem, 256 threads (8 warps),
// warp tile 64x32 (4x4 grid of m16n8k16, 2 ks-steps/chunk, 3 split passes).
// Fragment-major smem (u32 units, per stage):
//   Ah @ 0     [2 ks][8 mt][32 lane][4]  = 2048 u32
//   Al @ 2048  same
//   Bh @ 4096  [2 ks][16 nt][32 lane][2] = 2048 u32
//   Bl @ 6144  same
// stage stride 8192 u32 (32 KB); 2 stages = 64 KB. All STS/LDS conflict-free.
// ---------------------------------------------------------------------------
#define STGU 8192
#define GEMM_SMEM (2 * STGU * 4)

__global__ __launch_bounds__(256, 1)
void tc_gemm(const float* __restrict__ A, const float* __restrict__ Bt,
             const float* __restrict__ bias, float* __restrict__ C, int N)
{
    extern __shared__ uint32_t smu[];
    const int tid = threadIdx.x;
    const int lane = tid & 31;
    const int wid = tid >> 5;
    const int wm = wid >> 2;       // 0..1
    const int wn = wid & 3;        // 0..3
    const int row0 = blockIdx.y * 128;
    const int col0 = blockIdx.x * 128;

    // ---- loader descriptors (smem index is simply f = tid + q*256) ----
    const float* aptr[8];
#pragma unroll
    for (int q = 0; q < 8; q++) {
        int f = tid + q * 256;
        int j = f & 3, ln = (f >> 2) & 31, mt = (f >> 7) & 7, ks = f >> 10;
        int r = mt * 16 + (ln >> 2) + (j & 1) * 8;
        int kk = ks * 16 + (ln & 3) * 2 + (j >> 1) * 8;
        aptr[q] = A + (size_t)(row0 + r) * GK + kk;
    }
    const float* bptr[8];
#pragma unroll
    for (int q = 0; q < 8; q++) {
        int g = tid + q * 256;
        int j = g & 1, ln = (g >> 1) & 31, nt = (g >> 6) & 15, ks = g >> 10;
        int n = nt * 8 + (ln >> 2);
        int kk = ks * 16 + (ln & 3) * 2 + j * 8;
        bptr[q] = Bt + (size_t)(col0 + n) * GK + kk;
    }

    float acc[4][4][4];
#pragma unroll
    for (int i = 0; i < 4; i++)
#pragma unroll
        for (int j = 0; j < 4; j++)
#pragma unroll
            for (int c = 0; c < 4; c++) acc[i][j][c] = 0.0f;

    float2 aval[8], bval[8];

    auto ldg = [&](int c) {
        const int o = c * 32;
#pragma unroll
        for (int q = 0; q < 8; q++) aval[q] = *(const float2*)(aptr[q] + o);
#pragma unroll
        for (int q = 0; q < 8; q++) bval[q] = *(const float2*)(bptr[q] + o);
    };

    auto sts = [&](int st) {
        uint32_t* base = smu + st * STGU;
#pragma unroll
        for (int q = 0; q < 8; q++) {
            float rx, ry;
            uint32_t h = pack_bf16_hi(aval[q].x, aval[q].y, rx, ry);
            base[tid + q * 256] = h;
            base[2048 + tid + q * 256] = pack_bf16(rx, ry);
        }
#pragma unroll
        for (int q = 0; q < 8; q++) {
            float rx, ry;
            uint32_t h = pack_bf16_hi(bval[q].x, bval[q].y, rx, ry);
            base[4096 + tid + q * 256] = h;
            base[6144 + tid + q * 256] = pack_bf16(rx, ry);
        }
    };

    ldg(0);
    sts(0);
    __syncthreads();

    for (int c = 0; c < GK / 32; c++) {
        const int st = c & 1;
        if (c + 1 < GK / 32) ldg(c + 1);

        const uint32_t* base = smu + st * STGU;
#pragma unroll
        for (int ks = 0; ks < 2; ks++) {
            uint4 AH[4], AL[4];
            uint2 BH[4], BL[4];
#pragma unroll
            for (int mi = 0; mi < 4; mi++) {
                uint32_t idx = ((ks * 8 + wm * 4 + mi) * 32 + lane) * 4;
                AH[mi] = *(const uint4*)(base + idx);
                AL[mi] = *(const uint4*)(base + 2048 + idx);
            }
#pragma unroll
            for (int ni = 0; ni < 4; ni++) {
                uint32_t idx = ((ks * 16 + wn * 4 + ni) * 32 + lane) * 2;
                BH[ni] = *(const uint2*)(base + 4096 + idx);
                BL[ni] = *(const uint2*)(base + 6144 + idx);
            }
#pragma unroll
            for (int mi = 0; mi < 4; mi++)
#pragma unroll
                for (int ni = 0; ni < 4; ni++)
                    mma16(acc[mi][ni], AH[mi], BH[ni]);
#pragma unroll
            for (int mi = 0; mi < 4; mi++)
#pragma unroll
                for (int ni = 0; ni < 4; ni++)
                    mma16(acc[mi][ni], AH[mi], BL[ni]);
#pragma unroll
            for (int mi = 0; mi < 4; mi++)
#pragma unroll
                for (int ni = 0; ni < 4; ni++)
                    mma16(acc[mi][ni], AL[mi], BH[ni]);
        }

        if (c + 1 < GK / 32) sts((c + 1) & 1);
        __syncthreads();
    }

    // ---- epilogue: acc -> C with bias ----
#pragma unroll
    for (int mi = 0; mi < 4; mi++) {
        const int m = row0 + wm * 64 + mi * 16 + (lane >> 2);
#pragma unroll
        for (int ni = 0; ni < 4; ni++) {
            const int n = col0 + wn * 32 + ni * 8 + (lane & 3) * 2;
            float2 bb = *(const float2*)(bias + n);
            float2 o0 = make_float2(acc[mi][ni][0] + bb.x, acc[mi][ni][1] + bb.y);
            float2 o1 = make_float2(acc[mi][ni][2] + bb.x, acc[mi][ni][3] + bb.y);
            *(float2*)(C + (size_t)m * N + n) = o0;
            *(float2*)(C + (size_t)(m + 8) * N + n) = o1;
        }
    }
}

// ---------------------------------------------------------------------------
// Flash attention (fp32, causal, online softmax).
// R4: smem reductions -> warp shuffles (tx lives in lane bits 0-3), barriers
// 5 -> 3 per tile, red[] buffer removed (smem 64 KB).
// ---------------------------------------------------------------------------
__global__ __launch_bounds__(256) void flash_kernel(
    const float* __restrict__ qkv, float* __restrict__ att)
{
    extern __shared__ float smf[];
    float* q_t = smf;            // 4096: d-major, swizzled, pre-scaled
    float* k_t = smf + 4096;     // 4096: d-major, swizzled
    float* v_s = smf + 8192;     // 4096: row-major [krow][d]
    float* p_s = smf + 12288;    // 4096: row-major [qrow][kcol]

    const int tid = threadIdx.x;
    const int tx = tid & 15;
    const int ty = tid >> 4;
    const int qt = blockIdx.x;
    const int h  = blockIdx.y;
    const int b  = blockIdx.z;
    const int q0 = qt * 64;

    const size_t row_stride = 3 * D_MODEL;
    const float* qbase = qkv + (size_t)b * SEQ * row_stride + h * HEAD_DIM;
    const float* kbase = qbase + D_MODEL;
    const float* vbase = qbase + 2 * D_MODEL;

    const int c4 = tid & 15;
    const int rb = tid >> 4;
    const int sw = (c4 & 7) << 2;

#pragma unroll
    for (int it = 0; it < 4; it++) {
        int rr = rb + it * 16;
        float4 v = *(const float4*)(qbase + (size_t)(q0 + rr) * row_stride + c4 * 4);
        int pr = rr ^ sw;
        q_t[(c4 * 4 + 0) * 64 + pr] = v.x * 0.125f;
        q_t[(c4 * 4 + 1) * 64 + pr] = v.y * 0.125f;
        q_t[(c4 * 4 + 2) * 64 + pr] = v.z * 0.125f;
        q_t[(c4 * 4 + 3) * 64 + pr] = v.w * 0.125f;
    }

    float m[4], l[4], o[4][4];
#pragma unroll
    for (int i = 0; i < 4; i++) {
        m[i] = -1e30f;
        l[i] = 0.0f;
#pragma unroll
        for (int j = 0; j < 4; j++) o[i][j] = 0.0f;
    }

    for (int t = 0; t <= qt; t++) {
        const int k0 = t * 64;

#pragma unroll
        for (int it = 0; it < 4; it++) {
            int rr = rb + it * 16;
            float4 kv4 = *(const float4*)(kbase + (size_t)(k0 + rr) * row_stride + c4 * 4);
            int pr = rr ^ sw;
            k_t[(c4 * 4 + 0) * 64 + pr] = kv4.x;
            k_t[(c4 * 4 + 1) * 64 + pr] = kv4.y;
            k_t[(c4 * 4 + 2) * 64 + pr] = kv4.z;
            k_t[(c4 * 4 + 3) * 64 + pr] = kv4.w;
            float4 vv4 = *(const float4*)(vbase + (size_t)(k0 + rr) * row_stride + c4 * 4);
            *(float4*)&v_s[rr * 64 + c4 * 4] = vv4;
        }
        __syncthreads();

        // ---- S = (Q*scale) @ K^T ----
        float s[4][4];
#pragma unroll
        for (int i = 0; i < 4; i++)
#pragma unroll
            for (int j = 0; j < 4; j++) s[i][j] = 0.0f;

#pragma unroll 16
        for (int d = 0; d < 64; d++) {
            int dsw = ((d >> 2) & 7) << 2;
            float4 qa = *(const float4*)&q_t[d * 64 + ((ty * 4) ^ dsw)];
            float4 ka = *(const float4*)&k_t[d * 64 + ((tx * 4) ^ dsw)];
            float qv[4] = {qa.x, qa.y, qa.z, qa.w};
            float kv[4] = {ka.x, ka.y, ka.z, ka.w};
#pragma unroll
            for (int i = 0; i < 4; i++)
#pragma unroll
                for (int j = 0; j < 4; j++)
                    s[i][j] = fmaf(qv[i], kv[j], s[i][j]);
        }

        if (t == qt) {
#pragma unroll
            for (int i = 0; i < 4; i++)
#pragma unroll
                for (int j = 0; j < 4; j++)
                    if (k0 + tx * 4 + j > q0 + ty * 4 + i) s[i][j] = -1e30f;
        }

        // ---- softmax via shuffles (row spread over lanes with same ty) ----
#pragma unroll
        for (int i = 0; i < 4; i++) {
            float mx = fmaxf(fmaxf(s[i][0], s[i][1]), fmaxf(s[i][2], s[i][3]));
            mx = fmaxf(mx, __shfl_xor_sync(0xffffffffu, mx, 1));
            mx = fmaxf(mx, __shfl_xor_sync(0xffffffffu, mx, 2));
            mx = fmaxf(mx, __shfl_xor_sync(0xffffffffu, mx, 4));
            mx = fmaxf(mx, __shfl_xor_sync(0xffffffffu, mx, 8));
            float mn = fmaxf(m[i], mx);
            float p0 = __expf(s[i][0] - mn);
            float p1 = __expf(s[i][1] - mn);
            float p2 = __expf(s[i][2] - mn);
            float p3 = __expf(s[i][3] - mn);
            float rs = (p0 + p1) + (p2 + p3);
            rs += __shfl_xor_sync(0xffffffffu, rs, 1);
            rs += __shfl_xor_sync(0xffffffffu, rs, 2);
            rs += __shfl_xor_sync(0xffffffffu, rs, 4);
            rs += __shfl_xor_sync(0xffffffffu, rs, 8);
            float alpha = __expf(m[i] - mn);
            l[i] = l[i] * alpha + rs;
            m[i] = mn;
#pragma unroll
            for (int j = 0; j < 4; j++) o[i][j] *= alpha;
            *(float4*)&p_s[(ty * 4 + i) * 64 + tx * 4] = make_float4(p0, p1, p2, p3);
        }
        __syncthreads();

        // ---- O += P @ V ----
#pragma unroll 8
        for (int kk4 = 0; kk4 < 64; kk4 += 4) {
            float pr4[4][4];
#pragma unroll
            for (int i = 0; i < 4; i++) {
                float4 pp = *(const float4*)&p_s[(ty * 4 + i) * 64 + kk4];
                pr4[i][0] = pp.x; pr4[i][1] = pp.y; pr4[i][2] = pp.z; pr4[i][3] = pp.w;
            }
#pragma unroll
            for (int kki = 0; kki < 4; kki++) {
                float4 vv = *(const float4*)&v_s[(kk4 + kki) * 64 + tx * 4];
                float vr[4] = {vv.x, vv.y, vv.z, vv.w};
#pragma unroll
                for (int i = 0; i < 4; i++)
#pragma unroll
                    for (int j = 0; j < 4; j++)
                        o[i][j] = fmaf(pr4[i][kki], vr[j], o[i][j]);
            }
        }
        __syncthreads();
    }

#pragma unroll
    for (int i = 0; i < 4; i++) {
        float inv = 1.0f / l[i];
        int qg = q0 + ty * 4 + i;
        float4 ov = make_float4(o[i][0] * inv, o[i][1] * inv,
                                o[i][2] * inv, o[i][3] * inv);
        *(float4*)&att[((size_t)(b * SEQ + qg)) * D_MODEL + h * HEAD_DIM + tx * 4] = ov;
    }
}

// ---------------------------------------------------------------------------
extern "C" void kernel_launch(void* const* d_in, const int* in_sizes, int n_in,
                              void* d_out, int out_size)
{
    const float* x      = (const float*)d_in[0];
    const float* w_qkv  = (const float*)d_in[1];
    const float* b_qkv  = (const float*)d_in[2];
    const float* w_proj = (const float*)d_in[3];
    const float* b_proj = (const float*)d_in[4];
    float* out = (float*)d_out;

    float *qkv = nullptr, *att = nullptr, *wqkvT = nullptr, *wprojT = nullptr;
    cudaGetSymbolAddress((void**)&qkv, g_qkv);
    cudaGetSymbolAddress((void**)&att, g_att);
    cudaGetSymbolAddress((void**)&wqkvT, g_wqkv_t);
    cudaGetSymbolAddress((void**)&wprojT, g_wproj_t);

    const int M = BATCH * SEQ;  // 4096
    const int flash_smem = 4 * 64 * 64 * sizeof(float);  // 65536
    cudaFuncSetAttribute(flash_kernel,
                         cudaFuncAttributeMaxDynamicSharedMemorySize, flash_smem);
    cudaFuncSetAttribute(tc_gemm,
                         cudaFuncAttributeMaxDynamicSharedMemorySize, GEMM_SMEM);

    // 0) weight transposes (W^T: [N][K], K contiguous)
    transpose_k<<<dim3(3 * D_MODEL / 32, D_MODEL / 32), dim3(32, 8)>>>(
        w_qkv, wqkvT, D_MODEL, 3 * D_MODEL);
    transpose_k<<<dim3(D_MODEL / 32, D_MODEL / 32), dim3(32, 8)>>>(
        w_proj, wprojT, D_MODEL, D_MODEL);

    // 1) QKV GEMM (bf16 3x-split mma): [4096,1024] @ [1024,3072]
    tc_gemm<<<dim3(3 * D_MODEL / 128, M / 128), 256, GEMM_SMEM>>>(
        x, wqkvT, b_qkv, qkv, 3 * D_MODEL);

    // 2) Causal flash attention
    flash_kernel<<<dim3(SEQ / 64, N_HEADS, BATCH), 256, flash_smem>>>(qkv, att);

    // 3) Output projection: [4096,1024] @ [1024,1024]
    tc_gemm<<<dim3(D_MODEL / 128, M / 128), 256, GEMM_SMEM>>>(
        att, wprojT, b_proj, out, D_MODEL);
}

// round 5
// speedup vs baseline: 2.3741x; 1.6695x over previous
#include <cuda_runtime.h>
#include <cuda_bf16.h>
#include <cstdint>

#define D_MODEL 1024
#define N_HEADS 16
#define HEAD_DIM 64
#define SEQ 2048
#define BATCH 2
#define GK 1024

// Scratch (allocation-free rule: __device__ globals)
__device__ float g_qkv[BATCH * SEQ * 3 * D_MODEL];   // [B,S,3D]
__device__ float g_att[BATCH * SEQ * D_MODEL];       // [B,S,D]
__device__ float g_wqkv_t[3 * D_MODEL * D_MODEL];    // [3072][1024]  (W^T)
__device__ float g_wproj_t[D_MODEL * D_MODEL];       // [1024][1024]  (W^T)

__device__ __forceinline__ uint32_t pack_bf16_hi(float x, float y,
                                                 float& rx, float& ry) {
    __nv_bfloat16 hx = __float2bfloat16(x);
    __nv_bfloat16 hy = __float2bfloat16(y);
    rx = x - __bfloat162float(hx);
    ry = y - __bfloat162float(hy);
    __nv_bfloat162 p = __halves2bfloat162(hx, hy);   // lo half = x, hi half = y
    return *reinterpret_cast<uint32_t*>(&p);
}
__device__ __forceinline__ uint32_t pack_bf16(float x, float y) {
    __nv_bfloat162 p = __floats2bfloat162_rn(x, y);
    return *reinterpret_cast<uint32_t*>(&p);
}

__device__ __forceinline__ void mma16(float* d, const uint4& a, const uint2& b) {
    asm volatile(
        "mma.sync.aligned.m16n8k16.row.col.f32.bf16.bf16.f32 "
        "{%0,%1,%2,%3}, {%4,%5,%6,%7}, {%8,%9}, {%0,%1,%2,%3};"
        : "+f"(d[0]), "+f"(d[1]), "+f"(d[2]), "+f"(d[3])
        : "r"(a.x), "r"(a.y), "r"(a.z), "r"(a.w), "r"(b.x), "r"(b.y));
}

// ---------------------------------------------------------------------------
// Weight transpose: out[c][r] = in[r][c]
// ---------------------------------------------------------------------------
__global__ __launch_bounds__(256) void transpose_k(const float* __restrict__ in,
                                                   float* __restrict__ out,
                                                   int R, int C) {
    __shared__ float t[32][33];
    int c0 = blockIdx.x * 32, r0 = blockIdx.y * 32;
    int x = threadIdx.x, y = threadIdx.y;
#pragma unroll
    for (int i = 0; i < 32; i += 8)
        t[y + i][x] = in[(size_t)(r0 + y + i) * C + c0 + x];
    __syncthreads();
#pragma unroll
    for (int i = 0; i < 32; i += 8)
        out[(size_t)(c0 + y + i) * R + r0 + x] = t[x][y + i];
}

// ---------------------------------------------------------------------------
// mma.sync bf16 GEMM (3x bf16 split): C[M,N] = A[M,K] @ Bt[N,K]^T + bias[N]
// (unchanged from R4 — measured ~300 TF/s effective)
// ---------------------------------------------------------------------------
#define STGU 8192
#define GEMM_SMEM (2 * STGU * 4)

__global__ __launch_bounds__(256, 1)
void tc_gemm(const float* __restrict__ A, const float* __restrict__ Bt,
             const float* __restrict__ bias, float* __restrict__ C, int N)
{
    extern __shared__ uint32_t smu[];
    const int tid = threadIdx.x;
    const int lane = tid & 31;
    const int wid = tid >> 5;
    const int wm = wid >> 2;
    const int wn = wid & 3;
    const int row0 = blockIdx.y * 128;
    const int col0 = blockIdx.x * 128;

    const float* aptr[8];
#pragma unroll
    for (int q = 0; q < 8; q++) {
        int f = tid + q * 256;
        int j = f & 3, ln = (f >> 2) & 31, mt = (f >> 7) & 7, ks = f >> 10;
        int r = mt * 16 + (ln >> 2) + (j & 1) * 8;
        int kk = ks * 16 + (ln & 3) * 2 + (j >> 1) * 8;
        aptr[q] = A + (size_t)(row0 + r) * GK + kk;
    }
    const float* bptr[8];
#pragma unroll
    for (int q = 0; q < 8; q++) {
        int g = tid + q * 256;
        int j = g & 1, ln = (g >> 1) & 31, nt = (g >> 6) & 15, ks = g >> 10;
        int n = nt * 8 + (ln >> 2);
        int kk = ks * 16 + (ln & 3) * 2 + j * 8;
        bptr[q] = Bt + (size_t)(col0 + n) * GK + kk;
    }

    float acc[4][4][4];
#pragma unroll
    for (int i = 0; i < 4; i++)
#pragma unroll
        for (int j = 0; j < 4; j++)
#pragma unroll
            for (int c = 0; c < 4; c++) acc[i][j][c] = 0.0f;

    float2 aval[8], bval[8];

    auto ldg = [&](int c) {
        const int o = c * 32;
#pragma unroll
        for (int q = 0; q < 8; q++) aval[q] = *(const float2*)(aptr[q] + o);
#pragma unroll
        for (int q = 0; q < 8; q++) bval[q] = *(const float2*)(bptr[q] + o);
    };

    auto sts = [&](int st) {
        uint32_t* base = smu + st * STGU;
#pragma unroll
        for (int q = 0; q < 8; q++) {
            float rx, ry;
            uint32_t h = pack_bf16_hi(aval[q].x, aval[q].y, rx, ry);
            base[tid + q * 256] = h;
            base[2048 + tid + q * 256] = pack_bf16(rx, ry);
        }
#pragma unroll
        for (int q = 0; q < 8; q++) {
            float rx, ry;
            uint32_t h = pack_bf16_hi(bval[q].x, bval[q].y, rx, ry);
            base[4096 + tid + q * 256] = h;
            base[6144 + tid + q * 256] = pack_bf16(rx, ry);
        }
    };

    ldg(0);
    sts(0);
    __syncthreads();

    for (int c = 0; c < GK / 32; c++) {
        const int st = c & 1;
        if (c + 1 < GK / 32) ldg(c + 1);

        const uint32_t* base = smu + st * STGU;
#pragma unroll
        for (int ks = 0; ks < 2; ks++) {
            uint4 AH[4], AL[4];
            uint2 BH[4], BL[4];
#pragma unroll
            for (int mi = 0; mi < 4; mi++) {
                uint32_t idx = ((ks * 8 + wm * 4 + mi) * 32 + lane) * 4;
                AH[mi] = *(const uint4*)(base + idx);
                AL[mi] = *(const uint4*)(base + 2048 + idx);
            }
#pragma unroll
            for (int ni = 0; ni < 4; ni++) {
                uint32_t idx = ((ks * 16 + wn * 4 + ni) * 32 + lane) * 2;
                BH[ni] = *(const uint2*)(base + 4096 + idx);
                BL[ni] = *(const uint2*)(base + 6144 + idx);
            }
#pragma unroll
            for (int mi = 0; mi < 4; mi++)
#pragma unroll
                for (int ni = 0; ni < 4; ni++)
                    mma16(acc[mi][ni], AH[mi], BH[ni]);
#pragma unroll
            for (int mi = 0; mi < 4; mi++)
#pragma unroll
                for (int ni = 0; ni < 4; ni++)
                    mma16(acc[mi][ni], AH[mi], BL[ni]);
#pragma unroll
            for (int mi = 0; mi < 4; mi++)
#pragma unroll
                for (int ni = 0; ni < 4; ni++)
                    mma16(acc[mi][ni], AL[mi], BH[ni]);
        }

        if (c + 1 < GK / 32) sts((c + 1) & 1);
        __syncthreads();
    }

#pragma unroll
    for (int mi = 0; mi < 4; mi++) {
        const int m = row0 + wm * 64 + mi * 16 + (lane >> 2);
#pragma unroll
        for (int ni = 0; ni < 4; ni++) {
            const int n = col0 + wn * 32 + ni * 8 + (lane & 3) * 2;
            float2 bb = *(const float2*)(bias + n);
            float2 o0 = make_float2(acc[mi][ni][0] + bb.x, acc[mi][ni][1] + bb.y);
            float2 o1 = make_float2(acc[mi][ni][2] + bb.x, acc[mi][ni][3] + bb.y);
            *(float2*)(C + (size_t)m * N + n) = o0;
            *(float2*)(C + (size_t)(m + 8) * N + n) = o1;
        }
    }
}

// ---------------------------------------------------------------------------
// Flash attention on tensor cores (bf16 3-split mma, fp32 softmax).
// CTA = 128 threads (4 warps); q-tile 64 rows (16 per warp); k-tile 64.
// Smem (u32): Kh[2048] Kl Vh Vl | Qh Ql  = 12288 u32 = 48 KB.
// Fragment-major layouts (m16n8k16):
//   Q (A-op): [4 ks][4 mt][32 lane][4]  — pairs along d, reg pattern a0..a7
//   K (B-op): [4 ks][8 nt][32 lane][2]  — n = kv row, k = d
//   V (B-op): [4 ks'][8 nt][32 lane][2] — n = d col, k = kv (pairs along kv)
// P stays in registers: S C-fragment == PV A-fragment (identity remap).
// ---------------------------------------------------------------------------
#define FLASH_SMEM (12288 * 4)

__global__ __launch_bounds__(128, 3) void flash_mma(
    const float* __restrict__ qkv, float* __restrict__ att)
{
    extern __shared__ uint32_t su[];
    uint32_t* Kh = su;
    uint32_t* Kl = su + 2048;
    uint32_t* Vh = su + 4096;
    uint32_t* Vl = su + 6144;
    uint32_t* Qh = su + 8192;
    uint32_t* Ql = su + 10240;

    const int tid = threadIdx.x;
    const int lane = tid & 31;
    const int wid = tid >> 5;                  // 0..3
    const int qt = gridDim.x - 1 - blockIdx.x; // heavy blocks first
    const int h  = blockIdx.y;
    const int b  = blockIdx.z;
    const int q0 = qt * 64;

    const size_t rs = 3 * D_MODEL;             // 3072
    const float* qbase = qkv + (size_t)b * SEQ * rs + h * HEAD_DIM;
    const float* kbase = qbase + D_MODEL;
    const float* vbase = qbase + 2 * D_MODEL;

    // ---- load Q fragments (once), pre-scaled by 1/8 ----
#pragma unroll
    for (int i = 0; i < 16; i++) {
        int f = tid + i * 128;
        int q = f & 3, ln = (f >> 2) & 31, mt = (f >> 7) & 3, ks = f >> 9;
        int r = mt * 16 + (ln >> 2) + (q & 1) * 8;
        int d = ks * 16 + (ln & 3) * 2 + (q >> 1) * 8;
        float2 v = *(const float2*)(qbase + (size_t)(q0 + r) * rs + d);
        v.x *= 0.125f; v.y *= 0.125f;
        float rx, ry;
        Qh[f] = pack_bf16_hi(v.x, v.y, rx, ry);
        Ql[f] = pack_bf16(rx, ry);
    }

    float o[8][4];
#pragma unroll
    for (int nt = 0; nt < 8; nt++)
#pragma unroll
        for (int c = 0; c < 4; c++) o[nt][c] = 0.0f;
    float m0 = -1e30f, m1 = -1e30f, l0 = 0.0f, l1 = 0.0f;

    const int rq0 = q0 + wid * 16 + (lane >> 2);   // global q row of c0/c1

    for (int t = 0; t <= qt; t++) {
        const int k0 = t * 64;
        __syncthreads();   // previous iter's readers done (also orders Q @ t=0)

        // ---- load K/V fragments ----
#pragma unroll
        for (int i = 0; i < 16; i++) {
            int f = tid + i * 128;
            int j = f & 1, ln = (f >> 1) & 31, nt = (f >> 6) & 7, ks = f >> 9;
            {   // K: n = kv row, k = d
                int row = k0 + nt * 8 + (ln >> 2);
                int d = ks * 16 + (ln & 3) * 2 + j * 8;
                float2 v = *(const float2*)(kbase + (size_t)row * rs + d);
                float rx, ry;
                Kh[f] = pack_bf16_hi(v.x, v.y, rx, ry);
                Kl[f] = pack_bf16(rx, ry);
            }
            {   // V: n = d col, k = kv (pair spans two kv rows)
                int kv = k0 + ks * 16 + (ln & 3) * 2 + j * 8;
                int d = nt * 8 + (ln >> 2);
                float vx = vbase[(size_t)kv * rs + d];
                float vy = vbase[(size_t)(kv + 1) * rs + d];
                float rx, ry;
                Vh[f] = pack_bf16_hi(vx, vy, rx, ry);
                Vl[f] = pack_bf16(rx, ry);
            }
        }
        __syncthreads();

        // ---- S = (Q/8) @ K^T  (3-split bf16) ----
        float s[8][4];
#pragma unroll
        for (int nt = 0; nt < 8; nt++)
#pragma unroll
            for (int c = 0; c < 4; c++) s[nt][c] = 0.0f;

#pragma unroll
        for (int ks = 0; ks < 4; ks++) {
            uint4 AH = *(const uint4*)&Qh[((ks * 4 + wid) * 32 + lane) * 4];
            uint4 AL = *(const uint4*)&Ql[((ks * 4 + wid) * 32 + lane) * 4];
            uint2 BH[8], BL[8];
#pragma unroll
            for (int nt = 0; nt < 8; nt++) {
                BH[nt] = *(const uint2*)&Kh[((ks * 8 + nt) * 32 + lane) * 2];
                BL[nt] = *(const uint2*)&Kl[((ks * 8 + nt) * 32 + lane) * 2];
            }
#pragma unroll
            for (int nt = 0; nt < 8; nt++) mma16(s[nt], AH, BH[nt]);
#pragma unroll
            for (int nt = 0; nt < 8; nt++) mma16(s[nt], AH, BL[nt]);
#pragma unroll
            for (int nt = 0; nt < 8; nt++) mma16(s[nt], AL, BH[nt]);
        }

        // ---- causal mask (diagonal tile only) ----
        if (t == qt) {
#pragma unroll
            for (int nt = 0; nt < 8; nt++) {
                int c = k0 + nt * 8 + (lane & 3) * 2;
                if (c > rq0)         s[nt][0] = -1e30f;
                if (c + 1 > rq0)     s[nt][1] = -1e30f;
                if (c > rq0 + 8)     s[nt][2] = -1e30f;
                if (c + 1 > rq0 + 8) s[nt][3] = -1e30f;
            }
        }

        // ---- online softmax (rows rq0, rq0+8; reduce over lane%4 group) ----
        float mx0 = -1e30f, mx1 = -1e30f;
#pragma unroll
        for (int nt = 0; nt < 8; nt++) {
            mx0 = fmaxf(mx0, fmaxf(s[nt][0], s[nt][1]));
            mx1 = fmaxf(mx1, fmaxf(s[nt][2], s[nt][3]));
        }
        mx0 = fmaxf(mx0, __shfl_xor_sync(0xffffffffu, mx0, 1));
        mx0 = fmaxf(mx0, __shfl_xor_sync(0xffffffffu, mx0, 2));
        mx1 = fmaxf(mx1, __shfl_xor_sync(0xffffffffu, mx1, 1));
        mx1 = fmaxf(mx1, __shfl_xor_sync(0xffffffffu, mx1, 2));
        float mn0 = fmaxf(m0, mx0), mn1 = fmaxf(m1, mx1);

        float sum0 = 0.0f, sum1 = 0.0f;
#pragma unroll
        for (int nt = 0; nt < 8; nt++) {
            s[nt][0] = __expf(s[nt][0] - mn0);
            s[nt][1] = __expf(s[nt][1] - mn0);
            s[nt][2] = __expf(s[nt][2] - mn1);
            s[nt][3] = __expf(s[nt][3] - mn1);
            sum0 += s[nt][0] + s[nt][1];
            sum1 += s[nt][2] + s[nt][3];
        }
        sum0 += __shfl_xor_sync(0xffffffffu, sum0, 1);
        sum0 += __shfl_xor_sync(0xffffffffu, sum0, 2);
        sum1 += __shfl_xor_sync(0xffffffffu, sum1, 1);
        sum1 += __shfl_xor_sync(0xffffffffu, sum1, 2);

        float a0 = __expf(m0 - mn0), a1 = __expf(m1 - mn1);
        l0 = l0 * a0 + sum0; m0 = mn0;
        l1 = l1 * a1 + sum1; m1 = mn1;
#pragma unroll
        for (int nt = 0; nt < 8; nt++) {
            o[nt][0] *= a0; o[nt][1] *= a0;
            o[nt][2] *= a1; o[nt][3] *= a1;
        }

        // ---- O += P @ V  (P from C-fragments, 3-split) ----
#pragma unroll
        for (int ks = 0; ks < 4; ks++) {
            float r0_, r1_, r2_, r3_;
            uint4 AH, AL;
            AH.x = pack_bf16_hi(s[2 * ks][0],     s[2 * ks][1],     r0_, r1_);
            AH.y = pack_bf16_hi(s[2 * ks][2],     s[2 * ks][3],     r2_, r3_);
            AL.x = pack_bf16(r0_, r1_);
            AL.y = pack_bf16(r2_, r3_);
            AH.z = pack_bf16_hi(s[2 * ks + 1][0], s[2 * ks + 1][1], r0_, r1_);
            AH.w = pack_bf16_hi(s[2 * ks + 1][2], s[2 * ks + 1][3], r2_, r3_);
            AL.z = pack_bf16(r0_, r1_);
            AL.w = pack_bf16(r2_, r3_);
            uint2 BH[8], BL[8];
#pragma unroll
            for (int nt = 0; nt < 8; nt++) {
                BH[nt] = *(const uint2*)&Vh[((ks * 8 + nt) * 32 + lane) * 2];
                BL[nt] = *(const uint2*)&Vl[((ks * 8 + nt) * 32 + lane) * 2];
            }
#pragma unroll
            for (int nt = 0; nt < 8; nt++) mma16(o[nt], AH, BH[nt]);
#pragma unroll
            for (int nt = 0; nt < 8; nt++) mma16(o[nt], AH, BL[nt]);
#pragma unroll
            for (int nt = 0; nt < 8; nt++) mma16(o[nt], AL, BH[nt]);
        }
    }

    // ---- normalize & write att[B,S,D] ----
    const float inv0 = 1.0f / l0, inv1 = 1.0f / l1;
#pragma unroll
    for (int nt = 0; nt < 8; nt++) {
        int col = h * HEAD_DIM + nt * 8 + (lane & 3) * 2;
        float* p0 = att + (size_t)(b * SEQ + rq0) * D_MODEL + col;
        float* p1 = att + (size_t)(b * SEQ + rq0 + 8) * D_MODEL + col;
        *(float2*)p0 = make_float2(o[nt][0] * inv0, o[nt][1] * inv0);
        *(float2*)p1 = make_float2(o[nt][2] * inv1, o[nt][3] * inv1);
    }
}

// ---------------------------------------------------------------------------
extern "C" void kernel_launch(void* const* d_in, const int* in_sizes, int n_in,
                              void* d_out, int out_size)
{
    const float* x      = (const float*)d_in[0];
    const float* w_qkv  = (const float*)d_in[1];
    const float* b_qkv  = (const float*)d_in[2];
    const float* w_proj = (const float*)d_in[3];
    const float* b_proj = (const float*)d_in[4];
    float* out = (float*)d_out;

    float *qkv = nullptr, *att = nullptr, *wqkvT = nullptr, *wprojT = nullptr;
    cudaGetSymbolAddress((void**)&qkv, g_qkv);
    cudaGetSymbolAddress((void**)&att, g_att);
    cudaGetSymbolAddress((void**)&wqkvT, g_wqkv_t);
    cudaGetSymbolAddress((void**)&wprojT, g_wproj_t);

    const int M = BATCH * SEQ;  // 4096
    cudaFuncSetAttribute(flash_mma,
                         cudaFuncAttributeMaxDynamicSharedMemorySize, FLASH_SMEM);
    cudaFuncSetAttribute(tc_gemm,
                         cudaFuncAttributeMaxDynamicSharedMemorySize, GEMM_SMEM);

    // 0) weight transposes (W^T: [N][K], K contiguous)
    transpose_k<<<dim3(3 * D_MODEL / 32, D_MODEL / 32), dim3(32, 8)>>>(
        w_qkv, wqkvT, D_MODEL, 3 * D_MODEL);
    transpose_k<<<dim3(D_MODEL / 32, D_MODEL / 32), dim3(32, 8)>>>(
        w_proj, wprojT, D_MODEL, D_MODEL);

    // 1) QKV GEMM (bf16 3x-split mma): [4096,1024] @ [1024,3072]
    tc_gemm<<<dim3(3 * D_MODEL / 128, M / 128), 256, GEMM_SMEM>>>(
        x, wqkvT, b_qkv, qkv, 3 * D_MODEL);

    // 2) Causal flash attention (tensor-core)
    flash_mma<<<dim3(SEQ / 64, N_HEADS, BATCH), 128, FLASH_SMEM>>>(qkv, att);

    // 3) Output projection: [4096,1024] @ [1024,1024]
    tc_gemm<<<dim3(D_MODEL / 128, M / 128), 256, GEMM_SMEM>>>(
        att, wprojT, b_proj, out, D_MODEL);
}

// round 6
// speedup vs baseline: 3.1924x; 1.3447x over previous
#include <cuda_runtime.h>
#include <cuda_fp16.h>
#include <cstdint>

#define D_MODEL 1024
#define N_HEADS 16
#define HEAD_DIM 64
#define SEQ 2048
#define BATCH 2
#define GK 1024

// Scratch (allocation-free rule: __device__ globals)
__device__ float g_qkv[BATCH * SEQ * 3 * D_MODEL];   // [B,S,3D]
__device__ float g_att[BATCH * SEQ * D_MODEL];       // [B,S,D]
__device__ float g_wqkv_t[3 * D_MODEL * D_MODEL];    // [3072][1024]  (W^T)
__device__ float g_wproj_t[D_MODEL * D_MODEL];       // [1024][1024]  (W^T)

__device__ __forceinline__ uint32_t pack_f16_hi(float x, float y,
                                                float& rx, float& ry) {
    __half hx = __float2half_rn(x);
    __half hy = __float2half_rn(y);
    rx = x - __half2float(hx);
    ry = y - __half2float(hy);
    __half2 p = __halves2half2(hx, hy);
    return *reinterpret_cast<uint32_t*>(&p);
}
__device__ __forceinline__ uint32_t pack_f16(float x, float y) {
    __half2 p = __floats2half2_rn(x, y);
    return *reinterpret_cast<uint32_t*>(&p);
}

__device__ __forceinline__ void mma16(float* d, const uint4& a, const uint2& b) {
    asm volatile(
        "mma.sync.aligned.m16n8k16.row.col.f32.f16.f16.f32 "
        "{%0,%1,%2,%3}, {%4,%5,%6,%7}, {%8,%9}, {%0,%1,%2,%3};"
        : "+f"(d[0]), "+f"(d[1]), "+f"(d[2]), "+f"(d[3])
        : "r"(a.x), "r"(a.y), "r"(a.z), "r"(a.w), "r"(b.x), "r"(b.y));
}

// ---------------------------------------------------------------------------
// Weight transpose: out[c][r] = in[r][c]
// ---------------------------------------------------------------------------
__global__ __launch_bounds__(256) void transpose_k(const float* __restrict__ in,
                                                   float* __restrict__ out,
                                                   int R, int C) {
    __shared__ float t[32][33];
    int c0 = blockIdx.x * 32, r0 = blockIdx.y * 32;
    int x = threadIdx.x, y = threadIdx.y;
#pragma unroll
    for (int i = 0; i < 32; i += 8)
        t[y + i][x] = in[(size_t)(r0 + y + i) * C + c0 + x];
    __syncthreads();
#pragma unroll
    for (int i = 0; i < 32; i += 8)
        out[(size_t)(c0 + y + i) * R + r0 + x] = t[x][y + i];
}

// ---------------------------------------------------------------------------
// mma.sync fp16 GEMM (2-pass split, exact-A): C = A @ Bt^T + bias
// C = (Ah + Al) @ fp16(Bt)^T  -> only B-quantization error (~2^-12).
// CTA tile 128x128, K-chunk 32, double-buffered, 256 threads, warp 64x32.
// Smem per stage (u32): Ah[2048] Al[2048] Bh[2048] = 6144 u32 (24 KB).
// ---------------------------------------------------------------------------
#define STGU 6144
#define GEMM_SMEM (2 * STGU * 4)

__global__ __launch_bounds__(256, 1)
void tc_gemm(const float* __restrict__ A, const float* __restrict__ Bt,
             const float* __restrict__ bias, float* __restrict__ C, int N)
{
    extern __shared__ uint32_t smu[];
    const int tid = threadIdx.x;
    const int lane = tid & 31;
    const int wid = tid >> 5;
    const int wm = wid >> 2;
    const int wn = wid & 3;
    const int row0 = blockIdx.y * 128;
    const int col0 = blockIdx.x * 128;

    const float* aptr[8];
#pragma unroll
    for (int q = 0; q < 8; q++) {
        int f = tid + q * 256;
        int j = f & 3, ln = (f >> 2) & 31, mt = (f >> 7) & 7, ks = f >> 10;
        int r = mt * 16 + (ln >> 2) + (j & 1) * 8;
        int kk = ks * 16 + (ln & 3) * 2 + (j >> 1) * 8;
        aptr[q] = A + (size_t)(row0 + r) * GK + kk;
    }
    const float* bptr[8];
#pragma unroll
    for (int q = 0; q < 8; q++) {
        int g = tid + q * 256;
        int j = g & 1, ln = (g >> 1) & 31, nt = (g >> 6) & 15, ks = g >> 10;
        int n = nt * 8 + (ln >> 2);
        int kk = ks * 16 + (ln & 3) * 2 + j * 8;
        bptr[q] = Bt + (size_t)(col0 + n) * GK + kk;
    }

    float acc[4][4][4];
#pragma unroll
    for (int i = 0; i < 4; i++)
#pragma unroll
        for (int j = 0; j < 4; j++)
#pragma unroll
            for (int c = 0; c < 4; c++) acc[i][j][c] = 0.0f;

    float2 aval[8], bval[8];

    auto ldg = [&](int c) {
        const int o = c * 32;
#pragma unroll
        for (int q = 0; q < 8; q++) aval[q] = *(const float2*)(aptr[q] + o);
#pragma unroll
        for (int q = 0; q < 8; q++) bval[q] = *(const float2*)(bptr[q] + o);
    };

    auto sts = [&](int st) {
        uint32_t* base = smu + st * STGU;
#pragma unroll
        for (int q = 0; q < 8; q++) {
            float rx, ry;
            uint32_t h = pack_f16_hi(aval[q].x, aval[q].y, rx, ry);
            base[tid + q * 256] = h;
            base[2048 + tid + q * 256] = pack_f16(rx, ry);
        }
#pragma unroll
        for (int q = 0; q < 8; q++)
            base[4096 + tid + q * 256] = pack_f16(bval[q].x, bval[q].y);
    };

    ldg(0);
    sts(0);
    __syncthreads();

    for (int c = 0; c < GK / 32; c++) {
        const int st = c & 1;
        if (c + 1 < GK / 32) ldg(c + 1);

        const uint32_t* base = smu + st * STGU;
#pragma unroll
        for (int ks = 0; ks < 2; ks++) {
            uint4 AH[4], AL[4];
            uint2 BH[4];
#pragma unroll
            for (int mi = 0; mi < 4; mi++) {
                uint32_t idx = ((ks * 8 + wm * 4 + mi) * 32 + lane) * 4;
                AH[mi] = *(const uint4*)(base + idx);
                AL[mi] = *(const uint4*)(base + 2048 + idx);
            }
#pragma unroll
            for (int ni = 0; ni < 4; ni++) {
                uint32_t idx = ((ks * 16 + wn * 4 + ni) * 32 + lane) * 2;
                BH[ni] = *(const uint2*)(base + 4096 + idx);
            }
#pragma unroll
            for (int mi = 0; mi < 4; mi++)
#pragma unroll
                for (int ni = 0; ni < 4; ni++)
                    mma16(acc[mi][ni], AH[mi], BH[ni]);
#pragma unroll
            for (int mi = 0; mi < 4; mi++)
#pragma unroll
                for (int ni = 0; ni < 4; ni++)
                    mma16(acc[mi][ni], AL[mi], BH[ni]);
        }

        if (c + 1 < GK / 32) sts((c + 1) & 1);
        __syncthreads();
    }

#pragma unroll
    for (int mi = 0; mi < 4; mi++) {
        const int m = row0 + wm * 64 + mi * 16 + (lane >> 2);
#pragma unroll
        for (int ni = 0; ni < 4; ni++) {
            const int n = col0 + wn * 32 + ni * 8 + (lane & 3) * 2;
            float2 bb = *(const float2*)(bias + n);
            float2 o0 = make_float2(acc[mi][ni][0] + bb.x, acc[mi][ni][1] + bb.y);
            float2 o1 = make_float2(acc[mi][ni][2] + bb.x, acc[mi][ni][3] + bb.y);
            *(float2*)(C + (size_t)m * N + n) = o0;
            *(float2*)(C + (size_t)(m + 8) * N + n) = o1;
        }
    }
}

// ---------------------------------------------------------------------------
// Flash attention on tensor cores (fp16 2-pass split, fp32 softmax).
// S = (Qh+Ql) @ fp16(K)^T ; O += (Ph+Pl) @ fp16(V)  (P split exact).
// CTA = 128 threads (4 warps); q-tile 64, k-tile 64.
// Smem (u32): Kh[2048] Vh[2048] Qh[2048] Ql[2048] = 8192 u32 = 32 KB.
// ---------------------------------------------------------------------------
#define FLASH_SMEM (8192 * 4)

__global__ __launch_bounds__(128, 3) void flash_mma(
    const float* __restrict__ qkv, float* __restrict__ att)
{
    extern __shared__ uint32_t su[];
    uint32_t* Kh = su;
    uint32_t* Vh = su + 2048;
    uint32_t* Qh = su + 4096;
    uint32_t* Ql = su + 6144;

    const int tid = threadIdx.x;
    const int lane = tid & 31;
    const int wid = tid >> 5;
    const int qt = gridDim.x - 1 - blockIdx.x;  // heavy blocks first
    const int h  = blockIdx.y;
    const int b  = blockIdx.z;
    const int q0 = qt * 64;

    const size_t rs = 3 * D_MODEL;
    const float* qbase = qkv + (size_t)b * SEQ * rs + h * HEAD_DIM;
    const float* kbase = qbase + D_MODEL;
    const float* vbase = qbase + 2 * D_MODEL;

    // ---- load Q fragments (once), pre-scaled by 1/8, exact hi/lo split ----
#pragma unroll
    for (int i = 0; i < 16; i++) {
        int f = tid + i * 128;
        int q = f & 3, ln = (f >> 2) & 31, mt = (f >> 7) & 3, ks = f >> 9;
        int r = mt * 16 + (ln >> 2) + (q & 1) * 8;
        int d = ks * 16 + (ln & 3) * 2 + (q >> 1) * 8;
        float2 v = *(const float2*)(qbase + (size_t)(q0 + r) * rs + d);
        v.x *= 0.125f; v.y *= 0.125f;
        float rx, ry;
        Qh[f] = pack_f16_hi(v.x, v.y, rx, ry);
        Ql[f] = pack_f16(rx, ry);
    }

    float o[8][4];
#pragma unroll
    for (int nt = 0; nt < 8; nt++)
#pragma unroll
        for (int c = 0; c < 4; c++) o[nt][c] = 0.0f;
    float m0 = -1e30f, m1 = -1e30f, l0 = 0.0f, l1 = 0.0f;

    const int rq0 = q0 + wid * 16 + (lane >> 2);

    for (int t = 0; t <= qt; t++) {
        const int k0 = t * 64;
        __syncthreads();   // previous iter's readers done (orders Q at t=0)

        // ---- load K/V fragments (fp16 hi only) ----
#pragma unroll
        for (int i = 0; i < 16; i++) {
            int f = tid + i * 128;
            int j = f & 1, ln = (f >> 1) & 31, nt = (f >> 6) & 7, ks = f >> 9;
            {   // K: n = kv row, k = d
                int row = k0 + nt * 8 + (ln >> 2);
                int d = ks * 16 + (ln & 3) * 2 + j * 8;
                float2 v = *(const float2*)(kbase + (size_t)row * rs + d);
                Kh[f] = pack_f16(v.x, v.y);
            }
            {   // V: n = d col, k = kv (pair spans two kv rows)
                int kv = k0 + ks * 16 + (ln & 3) * 2 + j * 8;
                int d = nt * 8 + (ln >> 2);
                float vx = vbase[(size_t)kv * rs + d];
                float vy = vbase[(size_t)(kv + 1) * rs + d];
                Vh[f] = pack_f16(vx, vy);
            }
        }
        __syncthreads();

        // ---- S = (Q/8) @ K^T  (2-pass fp16: Qh*Kh + Ql*Kh) ----
        float s[8][4];
#pragma unroll
        for (int nt = 0; nt < 8; nt++)
#pragma unroll
            for (int c = 0; c < 4; c++) s[nt][c] = 0.0f;

#pragma unroll
        for (int ks = 0; ks < 4; ks++) {
            uint4 AH = *(const uint4*)&Qh[((ks * 4 + wid) * 32 + lane) * 4];
            uint4 AL = *(const uint4*)&Ql[((ks * 4 + wid) * 32 + lane) * 4];
            uint2 BH[8];
#pragma unroll
            for (int nt = 0; nt < 8; nt++)
                BH[nt] = *(const uint2*)&Kh[((ks * 8 + nt) * 32 + lane) * 2];
#pragma unroll
            for (int nt = 0; nt < 8; nt++) mma16(s[nt], AH, BH[nt]);
#pragma unroll
            for (int nt = 0; nt < 8; nt++) mma16(s[nt], AL, BH[nt]);
        }

        // ---- causal mask (diagonal tile only) ----
        if (t == qt) {
#pragma unroll
            for (int nt = 0; nt < 8; nt++) {
                int c = k0 + nt * 8 + (lane & 3) * 2;
                if (c > rq0)         s[nt][0] = -1e30f;
                if (c + 1 > rq0)     s[nt][1] = -1e30f;
                if (c > rq0 + 8)     s[nt][2] = -1e30f;
                if (c + 1 > rq0 + 8) s[nt][3] = -1e30f;
            }
        }

        // ---- online softmax (rows rq0, rq0+8; reduce over lane%4 group) ----
        float mx0 = -1e30f, mx1 = -1e30f;
#pragma unroll
        for (int nt = 0; nt < 8; nt++) {
            mx0 = fmaxf(mx0, fmaxf(s[nt][0], s[nt][1]));
            mx1 = fmaxf(mx1, fmaxf(s[nt][2], s[nt][3]));
        }
        mx0 = fmaxf(mx0, __shfl_xor_sync(0xffffffffu, mx0, 1));
        mx0 = fmaxf(mx0, __shfl_xor_sync(0xffffffffu, mx0, 2));
        mx1 = fmaxf(mx1, __shfl_xor_sync(0xffffffffu, mx1, 1));
        mx1 = fmaxf(mx1, __shfl_xor_sync(0xffffffffu, mx1, 2));
        float mn0 = fmaxf(m0, mx0), mn1 = fmaxf(m1, mx1);

        float sum0 = 0.0f, sum1 = 0.0f;
#pragma unroll
        for (int nt = 0; nt < 8; nt++) {
            s[nt][0] = __expf(s[nt][0] - mn0);
            s[nt][1] = __expf(s[nt][1] - mn0);
            s[nt][2] = __expf(s[nt][2] - mn1);
            s[nt][3] = __expf(s[nt][3] - mn1);
            sum0 += s[nt][0] + s[nt][1];
            sum1 += s[nt][2] + s[nt][3];
        }
        sum0 += __shfl_xor_sync(0xffffffffu, sum0, 1);
        sum0 += __shfl_xor_sync(0xffffffffu, sum0, 2);
        sum1 += __shfl_xor_sync(0xffffffffu, sum1, 1);
        sum1 += __shfl_xor_sync(0xffffffffu, sum1, 2);

        float a0 = __expf(m0 - mn0), a1 = __expf(m1 - mn1);
        l0 = l0 * a0 + sum0; m0 = mn0;
        l1 = l1 * a1 + sum1; m1 = mn1;
#pragma unroll
        for (int nt = 0; nt < 8; nt++) {
            o[nt][0] *= a0; o[nt][1] *= a0;
            o[nt][2] *= a1; o[nt][3] *= a1;
        }

        // ---- O += P @ V  (P exact hi/lo split, 2 passes) ----
#pragma unroll
        for (int ks = 0; ks < 4; ks++) {
            float r0_, r1_, r2_, r3_;
            uint4 AH, AL;
            AH.x = pack_f16_hi(s[2 * ks][0],     s[2 * ks][1],     r0_, r1_);
            AH.y = pack_f16_hi(s[2 * ks][2],     s[2 * ks][3],     r2_, r3_);
            AL.x = pack_f16(r0_, r1_);
            AL.y = pack_f16(r2_, r3_);
            AH.z = pack_f16_hi(s[2 * ks + 1][0], s[2 * ks + 1][1], r0_, r1_);
            AH.w = pack_f16_hi(s[2 * ks + 1][2], s[2 * ks + 1][3], r2_, r3_);
            AL.z = pack_f16(r0_, r1_);
            AL.w = pack_f16(r2_, r3_);
            uint2 BH[8];
#pragma unroll
            for (int nt = 0; nt < 8; nt++)
                BH[nt] = *(const uint2*)&Vh[((ks * 8 + nt) * 32 + lane) * 2];
#pragma unroll
            for (int nt = 0; nt < 8; nt++) mma16(o[nt], AH, BH[nt]);
#pragma unroll
            for (int nt = 0; nt < 8; nt++) mma16(o[nt], AL, BH[nt]);
        }
    }

    // ---- normalize & write att[B,S,D] ----
    const float inv0 = 1.0f / l0, inv1 = 1.0f / l1;
#pragma unroll
    for (int nt = 0; nt < 8; nt++) {
        int col = h * HEAD_DIM + nt * 8 + (lane & 3) * 2;
        float* p0 = att + (size_t)(b * SEQ + rq0) * D_MODEL + col;
        float* p1 = att + (size_t)(b * SEQ + rq0 + 8) * D_MODEL + col;
        *(float2*)p0 = make_float2(o[nt][0] * inv0, o[nt][1] * inv0);
        *(float2*)p1 = make_float2(o[nt][2] * inv1, o[nt][3] * inv1);
    }
}

// ---------------------------------------------------------------------------
extern "C" void kernel_launch(void* const* d_in, const int* in_sizes, int n_in,
                              void* d_out, int out_size)
{
    const float* x      = (const float*)d_in[0];
    const float* w_qkv  = (const float*)d_in[1];
    const float* b_qkv  = (const float*)d_in[2];
    const float* w_proj = (const float*)d_in[3];
    const float* b_proj = (const float*)d_in[4];
    float* out = (float*)d_out;

    float *qkv = nullptr, *att = nullptr, *wqkvT = nullptr, *wprojT = nullptr;
    cudaGetSymbolAddress((void**)&qkv, g_qkv);
    cudaGetSymbolAddress((void**)&att, g_att);
    cudaGetSymbolAddress((void**)&wqkvT, g_wqkv_t);
    cudaGetSymbolAddress((void**)&wprojT, g_wproj_t);

    const int M = BATCH * SEQ;  // 4096
    cudaFuncSetAttribute(flash_mma,
                         cudaFuncAttributeMaxDynamicSharedMemorySize, FLASH_SMEM);
    cudaFuncSetAttribute(tc_gemm,
                         cudaFuncAttributeMaxDynamicSharedMemorySize, GEMM_SMEM);

    // 0) weight transposes (W^T: [N][K], K contiguous)
    transpose_k<<<dim3(3 * D_MODEL / 32, D_MODEL / 32), dim3(32, 8)>>>(
        w_qkv, wqkvT, D_MODEL, 3 * D_MODEL);
    transpose_k<<<dim3(D_MODEL / 32, D_MODEL / 32), dim3(32, 8)>>>(
        w_proj, wprojT, D_MODEL, D_MODEL);

    // 1) QKV GEMM (fp16 2-pass split): [4096,1024] @ [1024,3072]
    tc_gemm<<<dim3(3 * D_MODEL / 128, M / 128), 256, GEMM_SMEM>>>(
        x, wqkvT, b_qkv, qkv, 3 * D_MODEL);

    // 2) Causal flash attention (tensor-core, fp16 2-pass)
    flash_mma<<<dim3(SEQ / 64, N_HEADS, BATCH), 128, FLASH_SMEM>>>(qkv, att);

    // 3) Output projection: [4096,1024] @ [1024,1024]
    tc_gemm<<<dim3(D_MODEL / 128, M / 128), 256, GEMM_SMEM>>>(
        att, wprojT, b_proj, out, D_MODEL);
}

// round 8
// speedup vs baseline: 3.4322x; 1.0751x over previous
#include <cuda_runtime.h>
#include <cuda_fp16.h>
#include <cstdint>

#define D_MODEL 1024
#define N_HEADS 16
#define HEAD_DIM 64
#define SEQ 2048
#define BATCH 2
#define GK 1024

// Scratch (allocation-free rule: __device__ globals)
__device__ float g_qkv[BATCH * SEQ * 3 * D_MODEL];   // [B,S,3D]
__device__ float g_att[BATCH * SEQ * D_MODEL];       // [B,S,D]
__device__ float g_wqkv_t[3 * D_MODEL * D_MODEL];    // [3072][1024]  (W^T)
__device__ float g_wproj_t[D_MODEL * D_MODEL];       // [1024][1024]  (W^T)

__device__ __forceinline__ uint32_t pack_f16_hi(float x, float y,
                                                float& rx, float& ry) {
    __half hx = __float2half_rn(x);
    __half hy = __float2half_rn(y);
    rx = x - __half2float(hx);
    ry = y - __half2float(hy);
    __half2 p = __halves2half2(hx, hy);
    return *reinterpret_cast<uint32_t*>(&p);
}
__device__ __forceinline__ uint32_t pack_f16(float x, float y) {
    __half2 p = __floats2half2_rn(x, y);
    return *reinterpret_cast<uint32_t*>(&p);
}

__device__ __forceinline__ void mma16(float* d, const uint4& a, const uint2& b) {
    asm volatile(
        "mma.sync.aligned.m16n8k16.row.col.f32.f16.f16.f32 "
        "{%0,%1,%2,%3}, {%4,%5,%6,%7}, {%8,%9}, {%0,%1,%2,%3};"
        : "+f"(d[0]), "+f"(d[1]), "+f"(d[2]), "+f"(d[3])
        : "r"(a.x), "r"(a.y), "r"(a.z), "r"(a.w), "r"(b.x), "r"(b.y));
}

// ---------------------------------------------------------------------------
// Weight transpose: out[c][r] = in[r][c]
// ---------------------------------------------------------------------------
__global__ __launch_bounds__(256) void transpose_k(const float* __restrict__ in,
                                                   float* __restrict__ out,
                                                   int R, int C) {
    __shared__ float t[32][33];
    int c0 = blockIdx.x * 32, r0 = blockIdx.y * 32;
    int x = threadIdx.x, y = threadIdx.y;
#pragma unroll
    for (int i = 0; i < 32; i += 8)
        t[y + i][x] = in[(size_t)(r0 + y + i) * C + c0 + x];
    __syncthreads();
#pragma unroll
    for (int i = 0; i < 32; i += 8)
        out[(size_t)(c0 + y + i) * R + r0 + x] = t[x][y + i];
}

// ---------------------------------------------------------------------------
// mma.sync fp16 GEMM (single pass): C = fp16(A) @ fp16(Bt)^T + bias
// CTA tile 128x128, K-chunk 32, double-buffered, 256 threads, warp 64x32.
// Smem per stage (u32): Ah[2048] Bh[2048] = 4096 u32 (16 KB).
// ---------------------------------------------------------------------------
#define STGU 4096
#define GEMM_SMEM (2 * STGU * 4)

__global__ __launch_bounds__(256, 1)
void tc_gemm(const float* __restrict__ A, const float* __restrict__ Bt,
             const float* __restrict__ bias, float* __restrict__ C, int N)
{
    extern __shared__ uint32_t smu[];
    const int tid = threadIdx.x;
    const int lane = tid & 31;
    const int wid = tid >> 5;
    const int wm = wid >> 2;
    const int wn = wid & 3;
    const int row0 = blockIdx.y * 128;
    const int col0 = blockIdx.x * 128;

    const float* aptr[8];
#pragma unroll
    for (int q = 0; q < 8; q++) {
        int f = tid + q * 256;
        int j = f & 3, ln = (f >> 2) & 31, mt = (f >> 7) & 7, ks = f >> 10;
        int r = mt * 16 + (ln >> 2) + (j & 1) * 8;
        int kk = ks * 16 + (ln & 3) * 2 + (j >> 1) * 8;
        aptr[q] = A + (size_t)(row0 + r) * GK + kk;
    }
    const float* bptr[8];
#pragma unroll
    for (int q = 0; q < 8; q++) {
        int g = tid + q * 256;
        int j = g & 1, ln = (g >> 1) & 31, nt = (g >> 6) & 15, ks = g >> 10;
        int n = nt * 8 + (ln >> 2);
        int kk = ks * 16 + (ln & 3) * 2 + j * 8;
        bptr[q] = Bt + (size_t)(col0 + n) * GK + kk;
    }

    float acc[4][4][4];
#pragma unroll
    for (int i = 0; i < 4; i++)
#pragma unroll
        for (int j = 0; j < 4; j++)
#pragma unroll
            for (int c = 0; c < 4; c++) acc[i][j][c] = 0.0f;

    float2 aval[8], bval[8];

    auto ldg = [&](int c) {
        const int o = c * 32;
#pragma unroll
        for (int q = 0; q < 8; q++) aval[q] = *(const float2*)(aptr[q] + o);
#pragma unroll
        for (int q = 0; q < 8; q++) bval[q] = *(const float2*)(bptr[q] + o);
    };

    auto sts = [&](int st) {
        uint32_t* base = smu + st * STGU;
#pragma unroll
        for (int q = 0; q < 8; q++)
            base[tid + q * 256] = pack_f16(aval[q].x, aval[q].y);
#pragma unroll
        for (int q = 0; q < 8; q++)
            base[2048 + tid + q * 256] = pack_f16(bval[q].x, bval[q].y);
    };

    ldg(0);
    sts(0);
    __syncthreads();

    for (int c = 0; c < GK / 32; c++) {
        const int st = c & 1;
        if (c + 1 < GK / 32) ldg(c + 1);

        const uint32_t* base = smu + st * STGU;
#pragma unroll
        for (int ks = 0; ks < 2; ks++) {
            uint4 AH[4];
            uint2 BH[4];
#pragma unroll
            for (int mi = 0; mi < 4; mi++) {
                uint32_t idx = ((ks * 8 + wm * 4 + mi) * 32 + lane) * 4;
                AH[mi] = *(const uint4*)(base + idx);
            }
#pragma unroll
            for (int ni = 0; ni < 4; ni++) {
                uint32_t idx = ((ks * 16 + wn * 4 + ni) * 32 + lane) * 2;
                BH[ni] = *(const uint2*)(base + 2048 + idx);
            }
#pragma unroll
            for (int mi = 0; mi < 4; mi++)
#pragma unroll
                for (int ni = 0; ni < 4; ni++)
                    mma16(acc[mi][ni], AH[mi], BH[ni]);
        }

        if (c + 1 < GK / 32) sts((c + 1) & 1);
        __syncthreads();
    }

#pragma unroll
    for (int mi = 0; mi < 4; mi++) {
        const int m = row0 + wm * 64 + mi * 16 + (lane >> 2);
#pragma unroll
        for (int ni = 0; ni < 4; ni++) {
            const int n = col0 + wn * 32 + ni * 8 + (lane & 3) * 2;
            float2 bb = *(const float2*)(bias + n);
            float2 o0 = make_float2(acc[mi][ni][0] + bb.x, acc[mi][ni][1] + bb.y);
            float2 o1 = make_float2(acc[mi][ni][2] + bb.x, acc[mi][ni][3] + bb.y);
            *(float2*)(C + (size_t)m * N + n) = o0;
            *(float2*)(C + (size_t)(m + 8) * N + n) = o1;
        }
    }
}

// ---------------------------------------------------------------------------
// Flash attention on tensor cores (fp16, fp32 softmax).
// S = (Qh+Ql) @ fp16(K)^T ; O += (Ph+Pl) @ fp16(V)  (Q,P split exact).
// R7: double-buffered K/V smem stages + register prefetch of next tile's
// K/V during compute; ONE __syncthreads per k-tile.
// Smem (u32): stage0 {Kh 2048, Vh 2048} stage1 {...} Qh[2048] Ql[2048]
//           = 12288 u32 = 48 KB -> 3 CTAs/SM.
// ---------------------------------------------------------------------------
#define FLASH_SMEM (12288 * 4)

__global__ __launch_bounds__(128, 3) void flash_mma(
    const float* __restrict__ qkv, float* __restrict__ att)
{
    extern __shared__ uint32_t su[];
    uint32_t* Qh = su + 8192;
    uint32_t* Ql = su + 10240;

    const int tid = threadIdx.x;
    const int lane = tid & 31;
    const int wid = tid >> 5;
    const int qt = gridDim.x - 1 - blockIdx.x;  // heavy blocks first
    const int h  = blockIdx.y;
    const int b  = blockIdx.z;
    const int q0 = qt * 64;

    const size_t rs = 3 * D_MODEL;
    const float* qbase = qkv + (size_t)b * SEQ * rs + h * HEAD_DIM;
    const float* kbase = qbase + D_MODEL;
    const float* vbase = qbase + 2 * D_MODEL;

    // ---- load Q fragments (once), pre-scaled by 1/8, exact hi/lo split ----
#pragma unroll
    for (int i = 0; i < 16; i++) {
        int f = tid + i * 128;
        int q = f & 3, ln = (f >> 2) & 31, mt = (f >> 7) & 3, ks = f >> 9;
        int r = mt * 16 + (ln >> 2) + (q & 1) * 8;
        int d = ks * 16 + (ln & 3) * 2 + (q >> 1) * 8;
        float2 v = *(const float2*)(qbase + (size_t)(q0 + r) * rs + d);
        v.x *= 0.125f; v.y *= 0.125f;
        float rx, ry;
        Qh[f] = pack_f16_hi(v.x, v.y, rx, ry);
        Ql[f] = pack_f16(rx, ry);
    }

    // ---- K/V prefetch registers + loaders ----
    float2 kreg[16], vreg[16];
    auto ldg_kv = [&](int k0) {
#pragma unroll
        for (int i = 0; i < 16; i++) {
            int f = tid + i * 128;
            int j = f & 1, ln = (f >> 1) & 31, nt = (f >> 6) & 7, ks = f >> 9;
            int row = k0 + nt * 8 + (ln >> 2);          // K: n = kv row
            int d = ks * 16 + (ln & 3) * 2 + j * 8;
            kreg[i] = *(const float2*)(kbase + (size_t)row * rs + d);
            int kv = k0 + ks * 16 + (ln & 3) * 2 + j * 8;  // V: pair along kv
            int dv = nt * 8 + (ln >> 2);
            vreg[i].x = vbase[(size_t)kv * rs + dv];
            vreg[i].y = vbase[(size_t)(kv + 1) * rs + dv];
        }
    };
    auto sts_kv = [&](uint32_t* stage) {
#pragma unroll
        for (int i = 0; i < 16; i++) {
            int f = tid + i * 128;
            stage[f] = pack_f16(kreg[i].x, kreg[i].y);
            stage[2048 + f] = pack_f16(vreg[i].x, vreg[i].y);
        }
    };

    float o[8][4];
#pragma unroll
    for (int nt = 0; nt < 8; nt++)
#pragma unroll
        for (int c = 0; c < 4; c++) o[nt][c] = 0.0f;
    float m0 = -1e30f, m1 = -1e30f, l0 = 0.0f, l1 = 0.0f;

    const int rq0 = q0 + wid * 16 + (lane >> 2);

    ldg_kv(0);

    for (int t = 0; t <= qt; t++) {
        uint32_t* stage = su + (t & 1) * 4096;
        uint32_t* Kh = stage;
        uint32_t* Vh = stage + 2048;

        sts_kv(stage);
        __syncthreads();           // stage ready; also orders Q at t=0
        if (t < qt) ldg_kv((t + 1) * 64);   // prefetch overlaps compute below

        // ---- S = (Q/8) @ K^T  (Qh*Kh + Ql*Kh) ----
        float s[8][4];
#pragma unroll
        for (int nt = 0; nt < 8; nt++)
#pragma unroll
            for (int c = 0; c < 4; c++) s[nt][c] = 0.0f;

#pragma unroll
        for (int ks = 0; ks < 4; ks++) {
            uint4 AH = *(const uint4*)&Qh[((ks * 4 + wid) * 32 + lane) * 4];
            uint4 AL = *(const uint4*)&Ql[((ks * 4 + wid) * 32 + lane) * 4];
            uint2 BH[8];
#pragma unroll
            for (int nt = 0; nt < 8; nt++)
                BH[nt] = *(const uint2*)&Kh[((ks * 8 + nt) * 32 + lane) * 2];
#pragma unroll
            for (int nt = 0; nt < 8; nt++) mma16(s[nt], AH, BH[nt]);
#pragma unroll
            for (int nt = 0; nt < 8; nt++) mma16(s[nt], AL, BH[nt]);
        }

        // ---- causal mask (diagonal tile only) ----
        if (t == qt) {
            const int k0 = t * 64;
#pragma unroll
            for (int nt = 0; nt < 8; nt++) {
                int c = k0 + nt * 8 + (lane & 3) * 2;
                if (c > rq0)         s[nt][0] = -1e30f;
                if (c + 1 > rq0)     s[nt][1] = -1e30f;
                if (c > rq0 + 8)     s[nt][2] = -1e30f;
                if (c + 1 > rq0 + 8) s[nt][3] = -1e30f;
            }
        }

        // ---- online softmax ----
        float mx0 = -1e30f, mx1 = -1e30f;
#pragma unroll
        for (int nt = 0; nt < 8; nt++) {
            mx0 = fmaxf(mx0, fmaxf(s[nt][0], s[nt][1]));
            mx1 = fmaxf(mx1, fmaxf(s[nt][2], s[nt][3]));
        }
        mx0 = fmaxf(mx0, __shfl_xor_sync(0xffffffffu, mx0, 1));
        mx0 = fmaxf(mx0, __shfl_xor_sync(0xffffffffu, mx0, 2));
        mx1 = fmaxf(mx1, __shfl_xor_sync(0xffffffffu, mx1, 1));
        mx1 = fmaxf(mx1, __shfl_xor_sync(0xffffffffu, mx1, 2));
        float mn0 = fmaxf(m0, mx0), mn1 = fmaxf(m1, mx1);

        float sum0 = 0.0f, sum1 = 0.0f;
#pragma unroll
        for (int nt = 0; nt < 8; nt++) {
            s[nt][0] = __expf(s[nt][0] - mn0);
            s[nt][1] = __expf(s[nt][1] - mn0);
            s[nt][2] = __expf(s[nt][2] - mn1);
            s[nt][3] = __expf(s[nt][3] - mn1);
            sum0 += s[nt][0] + s[nt][1];
            sum1 += s[nt][2] + s[nt][3];
        }
        sum0 += __shfl_xor_sync(0xffffffffu, sum0, 1);
        sum0 += __shfl_xor_sync(0xffffffffu, sum0, 2);
        sum1 += __shfl_xor_sync(0xffffffffu, sum1, 1);
        sum1 += __shfl_xor_sync(0xffffffffu, sum1, 2);

        float a0 = __expf(m0 - mn0), a1 = __expf(m1 - mn1);
        l0 = l0 * a0 + sum0; m0 = mn0;
        l1 = l1 * a1 + sum1; m1 = mn1;
#pragma unroll
        for (int nt = 0; nt < 8; nt++) {
            o[nt][0] *= a0; o[nt][1] *= a0;
            o[nt][2] *= a1; o[nt][3] *= a1;
        }

        // ---- O += P @ V  (P exact hi/lo split, 2 passes) ----
#pragma unroll
        for (int ks = 0; ks < 4; ks++) {
            float r0_, r1_, r2_, r3_;
            uint4 AH, AL;
            AH.x = pack_f16_hi(s[2 * ks][0],     s[2 * ks][1],     r0_, r1_);
            AH.y = pack_f16_hi(s[2 * ks][2],     s[2 * ks][3],     r2_, r3_);
            AL.x = pack_f16(r0_, r1_);
            AL.y = pack_f16(r2_, r3_);
            AH.z = pack_f16_hi(s[2 * ks + 1][0], s[2 * ks + 1][1], r0_, r1_);
            AH.w = pack_f16_hi(s[2 * ks + 1][2], s[2 * ks + 1][3], r2_, r3_);
            AL.z = pack_f16(r0_, r1_);
            AL.w = pack_f16(r2_, r3_);
            uint2 BH[8];
#pragma unroll
            for (int nt = 0; nt < 8; nt++)
                BH[nt] = *(const uint2*)&Vh[((ks * 8 + nt) * 32 + lane) * 2];
#pragma unroll
            for (int nt = 0; nt < 8; nt++) mma16(o[nt], AH, BH[nt]);
#pragma unroll
            for (int nt = 0; nt < 8; nt++) mma16(o[nt], AL, BH[nt]);
        }
    }

    // ---- normalize & write att[B,S,D] ----
    const float inv0 = 1.0f / l0, inv1 = 1.0f / l1;
#pragma unroll
    for (int nt = 0; nt < 8; nt++) {
        int col = h * HEAD_DIM + nt * 8 + (lane & 3) * 2;
        float* p0 = att + (size_t)(b * SEQ + rq0) * D_MODEL + col;
        float* p1 = att + (size_t)(b * SEQ + rq0 + 8) * D_MODEL + col;
        *(float2*)p0 = make_float2(o[nt][0] * inv0, o[nt][1] * inv0);
        *(float2*)p1 = make_float2(o[nt][2] * inv1, o[nt][3] * inv1);
    }
}

// ---------------------------------------------------------------------------
extern "C" void kernel_launch(void* const* d_in, const int* in_sizes, int n_in,
                              void* d_out, int out_size)
{
    const float* x      = (const float*)d_in[0];
    const float* w_qkv  = (const float*)d_in[1];
    const float* b_qkv  = (const float*)d_in[2];
    const float* w_proj = (const float*)d_in[3];
    const float* b_proj = (const float*)d_in[4];
    float* out = (float*)d_out;

    float *qkv = nullptr, *att = nullptr, *wqkvT = nullptr, *wprojT = nullptr;
    cudaGetSymbolAddress((void**)&qkv, g_qkv);
    cudaGetSymbolAddress((void**)&att, g_att);
    cudaGetSymbolAddress((void**)&wqkvT, g_wqkv_t);
    cudaGetSymbolAddress((void**)&wprojT, g_wproj_t);

    const int M = BATCH * SEQ;  // 4096
    cudaFuncSetAttribute(flash_mma,
                         cudaFuncAttributeMaxDynamicSharedMemorySize, FLASH_SMEM);
    cudaFuncSetAttribute(tc_gemm,
                         cudaFuncAttributeMaxDynamicSharedMemorySize, GEMM_SMEM);

    // 0) weight transposes (W^T: [N][K], K contiguous)
    transpose_k<<<dim3(3 * D_MODEL / 32, D_MODEL / 32), dim3(32, 8)>>>(
        w_qkv, wqkvT, D_MODEL, 3 * D_MODEL);
    transpose_k<<<dim3(D_MODEL / 32, D_MODEL / 32), dim3(32, 8)>>>(
        w_proj, wprojT, D_MODEL, D_MODEL);

    // 1) QKV GEMM (fp16 single-pass): [4096,1024] @ [1024,3072]
    tc_gemm<<<dim3(3 * D_MODEL / 128, M / 128), 256, GEMM_SMEM>>>(
        x, wqkvT, b_qkv, qkv, 3 * D_MODEL);

    // 2) Causal flash attention (tensor-core, pipelined)
    flash_mma<<<dim3(SEQ / 64, N_HEADS, BATCH), 128, FLASH_SMEM>>>(qkv, att);

    // 3) Output projection: [4096,1024] @ [1024,1024]
    tc_gemm<<<dim3(D_MODEL / 128, M / 128), 256, GEMM_SMEM>>>(
        att, wprojT, b_proj, out, D_MODEL);
}

// round 9
// speedup vs baseline: 3.5533x; 1.0353x over previous
#include <cuda_runtime.h>
#include <cuda_fp16.h>
#include <cstdint>

#define D_MODEL 1024
#define N_HEADS 16
#define HEAD_DIM 64
#define SEQ 2048
#define BATCH 2
#define GK 1024

// Scratch (allocation-free rule: __device__ globals)
__device__ float g_qkv[BATCH * SEQ * 3 * D_MODEL];   // [B,S,3D]
__device__ float g_att[BATCH * SEQ * D_MODEL];       // [B,S,D]
__device__ float g_wqkv_t[3 * D_MODEL * D_MODEL];    // [3072][1024]  (W^T)
__device__ float g_wproj_t[D_MODEL * D_MODEL];       // [1024][1024]  (W^T)

__device__ __forceinline__ uint32_t pack_f16(float x, float y) {
    __half2 p = __floats2half2_rn(x, y);
    return *reinterpret_cast<uint32_t*>(&p);
}

__device__ __forceinline__ void mma16(float* d, const uint4& a, const uint2& b) {
    asm volatile(
        "mma.sync.aligned.m16n8k16.row.col.f32.f16.f16.f32 "
        "{%0,%1,%2,%3}, {%4,%5,%6,%7}, {%8,%9}, {%0,%1,%2,%3};"
        : "+f"(d[0]), "+f"(d[1]), "+f"(d[2]), "+f"(d[3])
        : "r"(a.x), "r"(a.y), "r"(a.z), "r"(a.w), "r"(b.x), "r"(b.y));
}

// ---------------------------------------------------------------------------
// Weight transpose: out[c][r] = in[r][c]
// ---------------------------------------------------------------------------
__global__ __launch_bounds__(256) void transpose_k(const float* __restrict__ in,
                                                   float* __restrict__ out,
                                                   int R, int C) {
    __shared__ float t[32][33];
    int c0 = blockIdx.x * 32, r0 = blockIdx.y * 32;
    int x = threadIdx.x, y = threadIdx.y;
#pragma unroll
    for (int i = 0; i < 32; i += 8)
        t[y + i][x] = in[(size_t)(r0 + y + i) * C + c0 + x];
    __syncthreads();
#pragma unroll
    for (int i = 0; i < 32; i += 8)
        out[(size_t)(c0 + y + i) * R + r0 + x] = t[x][y + i];
}

// ---------------------------------------------------------------------------
// mma.sync fp16 GEMM (single pass): C = fp16(A) @ fp16(Bt)^T + bias
// (unchanged from R8 — at the legacy-mma ceiling)
// ---------------------------------------------------------------------------
#define STGU 4096
#define GEMM_SMEM (2 * STGU * 4)

__global__ __launch_bounds__(256, 1)
void tc_gemm(const float* __restrict__ A, const float* __restrict__ Bt,
             const float* __restrict__ bias, float* __restrict__ C, int N)
{
    extern __shared__ uint32_t smu[];
    const int tid = threadIdx.x;
    const int lane = tid & 31;
    const int wid = tid >> 5;
    const int wm = wid >> 2;
    const int wn = wid & 3;
    const int row0 = blockIdx.y * 128;
    const int col0 = blockIdx.x * 128;

    const float* aptr[8];
#pragma unroll
    for (int q = 0; q < 8; q++) {
        int f = tid + q * 256;
        int j = f & 3, ln = (f >> 2) & 31, mt = (f >> 7) & 7, ks = f >> 10;
        int r = mt * 16 + (ln >> 2) + (j & 1) * 8;
        int kk = ks * 16 + (ln & 3) * 2 + (j >> 1) * 8;
        aptr[q] = A + (size_t)(row0 + r) * GK + kk;
    }
    const float* bptr[8];
#pragma unroll
    for (int q = 0; q < 8; q++) {
        int g = tid + q * 256;
        int j = g & 1, ln = (g >> 1) & 31, nt = (g >> 6) & 15, ks = g >> 10;
        int n = nt * 8 + (ln >> 2);
        int kk = ks * 16 + (ln & 3) * 2 + j * 8;
        bptr[q] = Bt + (size_t)(col0 + n) * GK + kk;
    }

    float acc[4][4][4];
#pragma unroll
    for (int i = 0; i < 4; i++)
#pragma unroll
        for (int j = 0; j < 4; j++)
#pragma unroll
            for (int c = 0; c < 4; c++) acc[i][j][c] = 0.0f;

    float2 aval[8], bval[8];

    auto ldg = [&](int c) {
        const int o = c * 32;
#pragma unroll
        for (int q = 0; q < 8; q++) aval[q] = *(const float2*)(aptr[q] + o);
#pragma unroll
        for (int q = 0; q < 8; q++) bval[q] = *(const float2*)(bptr[q] + o);
    };

    auto sts = [&](int st) {
        uint32_t* base = smu + st * STGU;
#pragma unroll
        for (int q = 0; q < 8; q++)
            base[tid + q * 256] = pack_f16(aval[q].x, aval[q].y);
#pragma unroll
        for (int q = 0; q < 8; q++)
            base[2048 + tid + q * 256] = pack_f16(bval[q].x, bval[q].y);
    };

    ldg(0);
    sts(0);
    __syncthreads();

    for (int c = 0; c < GK / 32; c++) {
        const int st = c & 1;
        if (c + 1 < GK / 32) ldg(c + 1);

        const uint32_t* base = smu + st * STGU;
#pragma unroll
        for (int ks = 0; ks < 2; ks++) {
            uint4 AH[4];
            uint2 BH[4];
#pragma unroll
            for (int mi = 0; mi < 4; mi++) {
                uint32_t idx = ((ks * 8 + wm * 4 + mi) * 32 + lane) * 4;
                AH[mi] = *(const uint4*)(base + idx);
            }
#pragma unroll
            for (int ni = 0; ni < 4; ni++) {
                uint32_t idx = ((ks * 16 + wn * 4 + ni) * 32 + lane) * 2;
                BH[ni] = *(const uint2*)(base + 2048 + idx);
            }
#pragma unroll
            for (int mi = 0; mi < 4; mi++)
#pragma unroll
                for (int ni = 0; ni < 4; ni++)
                    mma16(acc[mi][ni], AH[mi], BH[ni]);
        }

        if (c + 1 < GK / 32) sts((c + 1) & 1);
        __syncthreads();
    }

#pragma unroll
    for (int mi = 0; mi < 4; mi++) {
        const int m = row0 + wm * 64 + mi * 16 + (lane >> 2);
#pragma unroll
        for (int ni = 0; ni < 4; ni++) {
            const int n = col0 + wn * 32 + ni * 8 + (lane & 3) * 2;
            float2 bb = *(const float2*)(bias + n);
            float2 o0 = make_float2(acc[mi][ni][0] + bb.x, acc[mi][ni][1] + bb.y);
            float2 o1 = make_float2(acc[mi][ni][2] + bb.x, acc[mi][ni][3] + bb.y);
            *(float2*)(C + (size_t)m * N + n) = o0;
            *(float2*)(C + (size_t)(m + 8) * N + n) = o1;
        }
    }
}

// ---------------------------------------------------------------------------
// Flash attention on tensor cores (fp16 single-pass everywhere, fp32 softmax).
// R9: Q and P splits dropped — 64 mma/warp/ktile (was 128), pack ALU halved.
// Smem (u32): stage0 {Kh 2048, Vh 2048} stage1 {...} Qh[2048]
//           = 10240 u32 = 40 KB.
// ---------------------------------------------------------------------------
#define FLASH_SMEM (10240 * 4)

__global__ __launch_bounds__(128, 3) void flash_mma(
    const float* __restrict__ qkv, float* __restrict__ att)
{
    extern __shared__ uint32_t su[];
    uint32_t* Qh = su + 8192;

    const int tid = threadIdx.x;
    const int lane = tid & 31;
    const int wid = tid >> 5;
    const int qt = gridDim.x - 1 - blockIdx.x;  // heavy blocks first
    const int h  = blockIdx.y;
    const int b  = blockIdx.z;
    const int q0 = qt * 64;

    const size_t rs = 3 * D_MODEL;
    const float* qbase = qkv + (size_t)b * SEQ * rs + h * HEAD_DIM;
    const float* kbase = qbase + D_MODEL;
    const float* vbase = qbase + 2 * D_MODEL;

    // ---- load Q fragments (once), pre-scaled by 1/8 ----
#pragma unroll
    for (int i = 0; i < 16; i++) {
        int f = tid + i * 128;
        int q = f & 3, ln = (f >> 2) & 31, mt = (f >> 7) & 3, ks = f >> 9;
        int r = mt * 16 + (ln >> 2) + (q & 1) * 8;
        int d = ks * 16 + (ln & 3) * 2 + (q >> 1) * 8;
        float2 v = *(const float2*)(qbase + (size_t)(q0 + r) * rs + d);
        Qh[f] = pack_f16(v.x * 0.125f, v.y * 0.125f);
    }

    // ---- K/V prefetch registers + loaders ----
    float2 kreg[16], vreg[16];
    auto ldg_kv = [&](int k0) {
#pragma unroll
        for (int i = 0; i < 16; i++) {
            int f = tid + i * 128;
            int j = f & 1, ln = (f >> 1) & 31, nt = (f >> 6) & 7, ks = f >> 9;
            int row = k0 + nt * 8 + (ln >> 2);          // K: n = kv row
            int d = ks * 16 + (ln & 3) * 2 + j * 8;
            kreg[i] = *(const float2*)(kbase + (size_t)row * rs + d);
            int kv = k0 + ks * 16 + (ln & 3) * 2 + j * 8;  // V: pair along kv
            int dv = nt * 8 + (ln >> 2);
            vreg[i].x = vbase[(size_t)kv * rs + dv];
            vreg[i].y = vbase[(size_t)(kv + 1) * rs + dv];
        }
    };
    auto sts_kv = [&](uint32_t* stage) {
#pragma unroll
        for (int i = 0; i < 16; i++) {
            int f = tid + i * 128;
            stage[f] = pack_f16(kreg[i].x, kreg[i].y);
            stage[2048 + f] = pack_f16(vreg[i].x, vreg[i].y);
        }
    };

    float o[8][4];
#pragma unroll
    for (int nt = 0; nt < 8; nt++)
#pragma unroll
        for (int c = 0; c < 4; c++) o[nt][c] = 0.0f;
    float m0 = -1e30f, m1 = -1e30f, l0 = 0.0f, l1 = 0.0f;

    const int rq0 = q0 + wid * 16 + (lane >> 2);

    ldg_kv(0);

    for (int t = 0; t <= qt; t++) {
        uint32_t* stage = su + (t & 1) * 4096;
        uint32_t* Kh = stage;
        uint32_t* Vh = stage + 2048;

        sts_kv(stage);
        __syncthreads();           // stage ready; also orders Q at t=0
        if (t < qt) ldg_kv((t + 1) * 64);   // prefetch overlaps compute below

        // ---- S = (Q/8) @ K^T  (single pass) ----
        float s[8][4];
#pragma unroll
        for (int nt = 0; nt < 8; nt++)
#pragma unroll
            for (int c = 0; c < 4; c++) s[nt][c] = 0.0f;

#pragma unroll
        for (int ks = 0; ks < 4; ks++) {
            uint4 AH = *(const uint4*)&Qh[((ks * 4 + wid) * 32 + lane) * 4];
            uint2 BH[8];
#pragma unroll
            for (int nt = 0; nt < 8; nt++)
                BH[nt] = *(const uint2*)&Kh[((ks * 8 + nt) * 32 + lane) * 2];
#pragma unroll
            for (int nt = 0; nt < 8; nt++) mma16(s[nt], AH, BH[nt]);
        }

        // ---- causal mask (diagonal tile only) ----
        if (t == qt) {
            const int k0 = t * 64;
#pragma unroll
            for (int nt = 0; nt < 8; nt++) {
                int c = k0 + nt * 8 + (lane & 3) * 2;
                if (c > rq0)         s[nt][0] = -1e30f;
                if (c + 1 > rq0)     s[nt][1] = -1e30f;
                if (c > rq0 + 8)     s[nt][2] = -1e30f;
                if (c + 1 > rq0 + 8) s[nt][3] = -1e30f;
            }
        }

        // ---- online softmax ----
        float mx0 = -1e30f, mx1 = -1e30f;
#pragma unroll
        for (int nt = 0; nt < 8; nt++) {
            mx0 = fmaxf(mx0, fmaxf(s[nt][0], s[nt][1]));
            mx1 = fmaxf(mx1, fmaxf(s[nt][2], s[nt][3]));
        }
        mx0 = fmaxf(mx0, __shfl_xor_sync(0xffffffffu, mx0, 1));
        mx0 = fmaxf(mx0, __shfl_xor_sync(0xffffffffu, mx0, 2));
        mx1 = fmaxf(mx1, __shfl_xor_sync(0xffffffffu, mx1, 1));
        mx1 = fmaxf(mx1, __shfl_xor_sync(0xffffffffu, mx1, 2));
        float mn0 = fmaxf(m0, mx0), mn1 = fmaxf(m1, mx1);

        float sum0 = 0.0f, sum1 = 0.0f;
#pragma unroll
        for (int nt = 0; nt < 8; nt++) {
            s[nt][0] = __expf(s[nt][0] - mn0);
            s[nt][1] = __expf(s[nt][1] - mn0);
            s[nt][2] = __expf(s[nt][2] - mn1);
            s[nt][3] = __expf(s[nt][3] - mn1);
            sum0 += s[nt][0] + s[nt][1];
            sum1 += s[nt][2] + s[nt][3];
        }
        sum0 += __shfl_xor_sync(0xffffffffu, sum0, 1);
        sum0 += __shfl_xor_sync(0xffffffffu, sum0, 2);
        sum1 += __shfl_xor_sync(0xffffffffu, sum1, 1);
        sum1 += __shfl_xor_sync(0xffffffffu, sum1, 2);

        float a0 = __expf(m0 - mn0), a1 = __expf(m1 - mn1);
        l0 = l0 * a0 + sum0; m0 = mn0;
        l1 = l1 * a1 + sum1; m1 = mn1;
#pragma unroll
        for (int nt = 0; nt < 8; nt++) {
            o[nt][0] *= a0; o[nt][1] *= a0;
            o[nt][2] *= a1; o[nt][3] *= a1;
        }

        // ---- O += P @ V  (P quantized single pass) ----
#pragma unroll
        for (int ks = 0; ks < 4; ks++) {
            uint4 AH;
            AH.x = pack_f16(s[2 * ks][0],     s[2 * ks][1]);
            AH.y = pack_f16(s[2 * ks][2],     s[2 * ks][3]);
            AH.z = pack_f16(s[2 * ks + 1][0], s[2 * ks + 1][1]);
            AH.w = pack_f16(s[2 * ks + 1][2], s[2 * ks + 1][3]);
            uint2 BH[8];
#pragma unroll
            for (int nt = 0; nt < 8; nt++)
                BH[nt] = *(const uint2*)&Vh[((ks * 8 + nt) * 32 + lane) * 2];
#pragma unroll
            for (int nt = 0; nt < 8; nt++) mma16(o[nt], AH, BH[nt]);
        }
    }

    // ---- normalize & write att[B,S,D] ----
    const float inv0 = 1.0f / l0, inv1 = 1.0f / l1;
#pragma unroll
    for (int nt = 0; nt < 8; nt++) {
        int col = h * HEAD_DIM + nt * 8 + (lane & 3) * 2;
        float* p0 = att + (size_t)(b * SEQ + rq0) * D_MODEL + col;
        float* p1 = att + (size_t)(b * SEQ + rq0 + 8) * D_MODEL + col;
        *(float2*)p0 = make_float2(o[nt][0] * inv0, o[nt][1] * inv0);
        *(float2*)p1 = make_float2(o[nt][2] * inv1, o[nt][3] * inv1);
    }
}

// ---------------------------------------------------------------------------
extern "C" void kernel_launch(void* const* d_in, const int* in_sizes, int n_in,
                              void* d_out, int out_size)
{
    const float* x      = (const float*)d_in[0];
    const float* w_qkv  = (const float*)d_in[1];
    const float* b_qkv  = (const float*)d_in[2];
    const float* w_proj = (const float*)d_in[3];
    const float* b_proj = (const float*)d_in[4];
    float* out = (float*)d_out;

    float *qkv = nullptr, *att = nullptr, *wqkvT = nullptr, *wprojT = nullptr;
    cudaGetSymbolAddress((void**)&qkv, g_qkv);
    cudaGetSymbolAddress((void**)&att, g_att);
    cudaGetSymbolAddress((void**)&wqkvT, g_wqkv_t);
    cudaGetSymbolAddress((void**)&wprojT, g_wproj_t);

    const int M = BATCH * SEQ;  // 4096
    cudaFuncSetAttribute(flash_mma,
                         cudaFuncAttributeMaxDynamicSharedMemorySize, FLASH_SMEM);
    cudaFuncSetAttribute(tc_gemm,
                         cudaFuncAttributeMaxDynamicSharedMemorySize, GEMM_SMEM);

    // 0) weight transposes (W^T: [N][K], K contiguous)
    transpose_k<<<dim3(3 * D_MODEL / 32, D_MODEL / 32), dim3(32, 8)>>>(
        w_qkv, wqkvT, D_MODEL, 3 * D_MODEL);
    transpose_k<<<dim3(D_MODEL / 32, D_MODEL / 32), dim3(32, 8)>>>(
        w_proj, wprojT, D_MODEL, D_MODEL);

    // 1) QKV GEMM (fp16 single-pass): [4096,1024] @ [1024,3072]
    tc_gemm<<<dim3(3 * D_MODEL / 128, M / 128), 256, GEMM_SMEM>>>(
        x, wqkvT, b_qkv, qkv, 3 * D_MODEL);

    // 2) Causal flash attention (tensor-core, single-pass fp16)
    flash_mma<<<dim3(SEQ / 64, N_HEADS, BATCH), 128, FLASH_SMEM>>>(qkv, att);

    // 3) Output projection: [4096,1024] @ [1024,1024]
    tc_gemm<<<dim3(D_MODEL / 128, M / 128), 256, GEMM_SMEM>>>(
        att, wprojT, b_proj, out, D_MODEL);
}

// round 10
// speedup vs baseline: 7.1045x; 1.9994x over previous
#include <cuda_runtime.h>
#include <cuda_fp16.h>
#include <cstdint>

#define D_MODEL 1024
#define N_HEADS 16
#define HEAD_DIM 64
#define SEQ 2048
#define BATCH 2
#define GK 1024

// Scratch (allocation-free rule: __device__ globals)
__device__ float    g_qkv[BATCH * SEQ * 3 * D_MODEL];  // fp32 [B,S,3D]
__device__ uint32_t g_x16[2097152];     // x packed, A-frag
__device__ uint32_t g_wqkv16[1572864];  // W_qkv^T packed, B-frag
__device__ uint32_t g_wproj16[524288];  // W_proj^T packed, B-frag
__device__ uint32_t g_q16[2097152];     // per (b,h,qt): [4ks][4mt][lane][4]
__device__ uint32_t g_k16[2097152];     // per (b,h,kt): [4ks][8nt][lane][2]
__device__ uint32_t g_v16[2097152];     // per (b,h,kt): [4ks][8nt][lane][2]
__device__ uint32_t g_att16[2097152];   // attention out, A-frag (proj input)

__device__ __forceinline__ uint32_t pack_f16(float x, float y) {
    __half2 p = __floats2half2_rn(x, y);
    return *reinterpret_cast<uint32_t*>(&p);
}

__device__ __forceinline__ void mma16(float* d, const uint4& a, const uint2& b) {
    asm volatile(
        "mma.sync.aligned.m16n8k16.row.col.f32.f16.f16.f32 "
        "{%0,%1,%2,%3}, {%4,%5,%6,%7}, {%8,%9}, {%0,%1,%2,%3};"
        : "+f"(d[0]), "+f"(d[1]), "+f"(d[2]), "+f"(d[3])
        : "r"(a.x), "r"(a.y), "r"(a.z), "r"(a.w), "r"(b.x), "r"(b.y));
}

__device__ __forceinline__ void cp16(uint32_t dst, const void* src) {
    asm volatile("cp.async.cg.shared.global [%0], [%1], 16;"
                 :: "r"(dst), "l"(src) : "memory");
}
#define CP_COMMIT() asm volatile("cp.async.commit_group;" ::: "memory")
#define CP_WAIT1()  asm volatile("cp.async.wait_group 1;" ::: "memory")
#define CP_WAIT0()  asm volatile("cp.async.wait_group 0;" ::: "memory")

// ---------------------------------------------------------------------------
// pack_a: fp32 [M,1024] row-major -> A-frag fp16 u32 layout
//   [M/128 rowblk][32 chunk][2 ks][8 mt][32 lane][4 j]
// ---------------------------------------------------------------------------
__global__ __launch_bounds__(256) void pack_a(const float* __restrict__ A,
                                              uint32_t* __restrict__ out) {
    int id = blockIdx.x * 256 + threadIdx.x;
    int f = id & 2047;
    int j = f & 3, lane = (f >> 2) & 31, mt = (f >> 7) & 7, ks = f >> 10;
    int chunk = (id >> 11) & 31;
    int rowblk = id >> 16;
    int r = rowblk * 128 + mt * 16 + (lane >> 2) + (j & 1) * 8;
    int k0 = chunk * 32 + ks * 16 + (lane & 3) * 2 + (j >> 1) * 8;
    float2 v = *(const float2*)(A + (size_t)r * GK + k0);
    out[id] = pack_f16(v.x, v.y);
}

// ---------------------------------------------------------------------------
// pack_w: fp32 W [1024, N] row-major -> B-frag fp16 u32 layout
//   [N/128 colblk][32 chunk][2 ks][16 nt][32 lane][2 j]
// element (n,k) = W[k][n], packed pairs along k
// ---------------------------------------------------------------------------
__global__ __launch_bounds__(256) void pack_w(const float* __restrict__ W,
                                              uint32_t* __restrict__ out, int N) {
    int id = blockIdx.x * 256 + threadIdx.x;
    int f = id & 2047;
    int j = f & 1, lane = (f >> 1) & 31, nt = (f >> 6) & 15, ks = f >> 10;
    int chunk = (id >> 11) & 31;
    int colblk = id >> 16;
    int n = colblk * 128 + nt * 8 + (lane >> 2);
    int k0 = chunk * 32 + ks * 16 + (lane & 3) * 2 + j * 8;
    out[id] = pack_f16(W[(size_t)k0 * N + n], W[(size_t)(k0 + 1) * N + n]);
}

// ---------------------------------------------------------------------------
// repack_qkv: fp32 qkv [B,S,3D] -> q16 (A-frag, pre-scaled 1/8), k16, v16
// grid (32 tiles, 16 h, 2 b) x 128 threads
// ---------------------------------------------------------------------------
__global__ __launch_bounds__(128) void repack_qkv(
    const float* __restrict__ qkv, uint32_t* __restrict__ q16,
    uint32_t* __restrict__ k16, uint32_t* __restrict__ v16)
{
    int tile = blockIdx.x, h = blockIdx.y, b = blockIdx.z;
    int tid = threadIdx.x;
    const float* base = qkv + (size_t)b * SEQ * 3072;
    size_t doff = (((size_t)(b * 16 + h)) * 32 + tile) * 2048;
    uint32_t* qd = q16 + doff;
    uint32_t* kd = k16 + doff;
    uint32_t* vd = v16 + doff;

#pragma unroll
    for (int i = 0; i < 16; i++) {
        int f = tid + i * 128;
        {   // Q  [4ks][4mt][lane][4j], scaled by 1/8
            int j = f & 3, ln = (f >> 2) & 31, mt = (f >> 7) & 3, ks = f >> 9;
            int r = tile * 64 + mt * 16 + (ln >> 2) + (j & 1) * 8;
            int d = h * 64 + ks * 16 + (ln & 3) * 2 + (j >> 1) * 8;
            float2 v = *(const float2*)(base + (size_t)r * 3072 + d);
            qd[f] = pack_f16(v.x * 0.125f, v.y * 0.125f);
        }
        {   // K  [4ks][8nt][lane][2j]  (n = kv row, k = d)
            int j = f & 1, ln = (f >> 1) & 31, nt = (f >> 6) & 7, ks = f >> 9;
            int r = tile * 64 + nt * 8 + (ln >> 2);
            int d = 1024 + h * 64 + ks * 16 + (ln & 3) * 2 + j * 8;
            float2 v = *(const float2*)(base + (size_t)r * 3072 + d);
            kd[f] = pack_f16(v.x, v.y);
        }
        {   // V  [4ks][8nt][lane][2j]  (n = d col, k = kv; pair along kv)
            int j = f & 1, ln = (f >> 1) & 31, nt = (f >> 6) & 7, ks = f >> 9;
            int kv = tile * 64 + ks * 16 + (ln & 3) * 2 + j * 8;
            int d = 2048 + h * 64 + nt * 8 + (ln >> 2);
            vd[f] = pack_f16(base[(size_t)kv * 3072 + d],
                             base[(size_t)(kv + 1) * 3072 + d]);
        }
    }
}

// ---------------------------------------------------------------------------
// tc_gemm: fp16 pre-packed operands, cp.async 3-stage, 2 CTAs/SM.
// C[M,N] = A @ B^T + bias (fp32 out). CTA 128x128, chunk K=32.
// stage (16 KB): A-frag 2048 u32 | B-frag 2048 u32
// ---------------------------------------------------------------------------
#define GEMM_SMEM (3 * 16384)

__global__ __launch_bounds__(256, 2)
void tc_gemm(const uint32_t* __restrict__ A16, const uint32_t* __restrict__ B16,
             const float* __restrict__ bias, float* __restrict__ C, int N)
{
    extern __shared__ uint32_t smu[];
    const int tid = threadIdx.x;
    const int lane = tid & 31;
    const int wid = tid >> 5;
    const int wm = wid >> 2;
    const int wn = wid & 3;
    const int row0 = blockIdx.y * 128;
    const int col0 = blockIdx.x * 128;

    const uint32_t* Ab = A16 + (size_t)blockIdx.y * 32 * 2048;
    const uint32_t* Bb = B16 + (size_t)blockIdx.x * 32 * 2048;
    const uint32_t smaddr = (uint32_t)__cvta_generic_to_shared(smu);

    auto cp_chunk = [&](int c, int s) {
        uint32_t d = smaddr + s * 16384 + tid * 16;
        const char* sa = (const char*)(Ab + c * 2048) + tid * 16;
        const char* sb = (const char*)(Bb + c * 2048) + tid * 16;
        cp16(d, sa);
        cp16(d + 4096, sa + 4096);
        cp16(d + 8192, sb);
        cp16(d + 12288, sb + 4096);
    };

    float acc[4][4][4];
#pragma unroll
    for (int i = 0; i < 4; i++)
#pragma unroll
        for (int j = 0; j < 4; j++)
#pragma unroll
            for (int c = 0; c < 4; c++) acc[i][j][c] = 0.0f;

    cp_chunk(0, 0);
    CP_COMMIT();

    for (int c = 0; c < 32; c++) {
        if (c < 31) {
            cp_chunk(c + 1, (c + 1) % 3);
            CP_COMMIT();
            CP_WAIT1();
        } else {
            CP_WAIT0();
        }
        __syncthreads();

        const uint32_t* base = smu + (c % 3) * 4096;
#pragma unroll
        for (int ks = 0; ks < 2; ks++) {
            uint4 AH[4];
            uint2 BH[4];
#pragma unroll
            for (int mi = 0; mi < 4; mi++)
                AH[mi] = *(const uint4*)&base[((ks * 8 + wm * 4 + mi) * 32 + lane) * 4];
#pragma unroll
            for (int ni = 0; ni < 4; ni++)
                BH[ni] = *(const uint2*)&base[2048 + ((ks * 16 + wn * 4 + ni) * 32 + lane) * 2];
#pragma unroll
            for (int mi = 0; mi < 4; mi++)
#pragma unroll
                for (int ni = 0; ni < 4; ni++)
                    mma16(acc[mi][ni], AH[mi], BH[ni]);
        }
    }

    // epilogue: bias + fp32 store
#pragma unroll
    for (int mi = 0; mi < 4; mi++) {
        const int m = row0 + wm * 64 + mi * 16 + (lane >> 2);
#pragma unroll
        for (int ni = 0; ni < 4; ni++) {
            const int n = col0 + wn * 32 + ni * 8 + (lane & 3) * 2;
            float2 bb = *(const float2*)(bias + n);
            float2 o0 = make_float2(acc[mi][ni][0] + bb.x, acc[mi][ni][1] + bb.y);
            float2 o1 = make_float2(acc[mi][ni][2] + bb.x, acc[mi][ni][3] + bb.y);
            *(float2*)(C + (size_t)m * N + n) = o0;
            *(float2*)(C + (size_t)(m + 8) * N + n) = o1;
        }
    }
}

// ---------------------------------------------------------------------------
// flash_mma v3: Q in registers, K/V via cp.async 3-stage, att16 out (A-frag).
// CTA 128 threads / 4 warps, q-tile 64, k-tile 64. smem = 3 x 16 KB.
// ---------------------------------------------------------------------------
#define FLASH_SMEM (3 * 16384)

__global__ __launch_bounds__(128, 4) void flash_mma(
    const uint32_t* __restrict__ q16, const uint32_t* __restrict__ k16,
    const uint32_t* __restrict__ v16, uint32_t* __restrict__ att16)
{
    extern __shared__ uint32_t su[];
    const int tid = threadIdx.x;
    const int lane = tid & 31;
    const int wid = tid >> 5;
    const int qt = gridDim.x - 1 - blockIdx.x;   // heavy blocks first
    const int h  = blockIdx.y;
    const int b  = blockIdx.z;

    const size_t bh = ((size_t)(b * 16 + h)) * 32;
    const uint32_t* kg = k16 + bh * 2048;
    const uint32_t* vg = v16 + bh * 2048;
    const uint32_t* qg = q16 + (bh + qt) * 2048;
    const uint32_t smaddr = (uint32_t)__cvta_generic_to_shared(su);

    // Q fragments in registers (warp owns mt = wid)
    uint4 QR[4];
#pragma unroll
    for (int ks = 0; ks < 4; ks++)
        QR[ks] = *(const uint4*)(qg + ((ks * 4 + wid) * 32 + lane) * 4);

    auto cp_tile = [&](int kt, int s) {
        uint32_t d = smaddr + s * 16384 + tid * 16;
        const char* sk = (const char*)(kg + kt * 2048) + tid * 16;
        const char* sv = (const char*)(vg + kt * 2048) + tid * 16;
#pragma unroll
        for (int r = 0; r < 4; r++) cp16(d + r * 2048, sk + r * 2048);
#pragma unroll
        for (int r = 0; r < 4; r++) cp16(d + 8192 + r * 2048, sv + r * 2048);
    };

    float o[8][4];
#pragma unroll
    for (int nt = 0; nt < 8; nt++)
#pragma unroll
        for (int c = 0; c < 4; c++) o[nt][c] = 0.0f;
    float m0 = -1e30f, m1 = -1e30f, l0 = 0.0f, l1 = 0.0f;

    const int rq0 = qt * 64 + wid * 16 + (lane >> 2);

    cp_tile(0, 0);
    CP_COMMIT();

    int scur = 0, snxt = 1;
    for (int t = 0; t <= qt; t++) {
        if (t < qt) {
            cp_tile(t + 1, snxt);
            CP_COMMIT();
            CP_WAIT1();
        } else {
            CP_WAIT0();
        }
        __syncthreads();

        const uint32_t* Kst = su + scur * 4096;
        const uint32_t* Vst = Kst + 2048;

        // ---- S = (Q/8) @ K^T ----
        float s[8][4];
#pragma unroll
        for (int nt = 0; nt < 8; nt++)
#pragma unroll
            for (int c = 0; c < 4; c++) s[nt][c] = 0.0f;

#pragma unroll
        for (int ks = 0; ks < 4; ks++) {
            uint2 BH[8];
#pragma unroll
            for (int nt = 0; nt < 8; nt++)
                BH[nt] = *(const uint2*)&Kst[((ks * 8 + nt) * 32 + lane) * 2];
#pragma unroll
            for (int nt = 0; nt < 8; nt++) mma16(s[nt], QR[ks], BH[nt]);
        }

        // ---- causal mask (diagonal tile only) ----
        if (t == qt) {
            const int k0 = t * 64;
#pragma unroll
            for (int nt = 0; nt < 8; nt++) {
                int c = k0 + nt * 8 + (lane & 3) * 2;
                if (c > rq0)         s[nt][0] = -1e30f;
                if (c + 1 > rq0)     s[nt][1] = -1e30f;
                if (c > rq0 + 8)     s[nt][2] = -1e30f;
                if (c + 1 > rq0 + 8) s[nt][3] = -1e30f;
            }
        }

        // ---- online softmax ----
        float mx0 = -1e30f, mx1 = -1e30f;
#pragma unroll
        for (int nt = 0; nt < 8; nt++) {
            mx0 = fmaxf(mx0, fmaxf(s[nt][0], s[nt][1]));
            mx1 = fmaxf(mx1, fmaxf(s[nt][2], s[nt][3]));
        }
        mx0 = fmaxf(mx0, __shfl_xor_sync(0xffffffffu, mx0, 1));
        mx0 = fmaxf(mx0, __shfl_xor_sync(0xffffffffu, mx0, 2));
        mx1 = fmaxf(mx1, __shfl_xor_sync(0xffffffffu, mx1, 1));
        mx1 = fmaxf(mx1, __shfl_xor_sync(0xffffffffu, mx1, 2));
        float mn0 = fmaxf(m0, mx0), mn1 = fmaxf(m1, mx1);

        float sum0 = 0.0f, sum1 = 0.0f;
#pragma unroll
        for (int nt = 0; nt < 8; nt++) {
            s[nt][0] = __expf(s[nt][0] - mn0);
            s[nt][1] = __expf(s[nt][1] - mn0);
            s[nt][2] = __expf(s[nt][2] - mn1);
            s[nt][3] = __expf(s[nt][3] - mn1);
            sum0 += s[nt][0] + s[nt][1];
            sum1 += s[nt][2] + s[nt][3];
        }
        sum0 += __shfl_xor_sync(0xffffffffu, sum0, 1);
        sum0 += __shfl_xor_sync(0xffffffffu, sum0, 2);
        sum1 += __shfl_xor_sync(0xffffffffu, sum1, 1);
        sum1 += __shfl_xor_sync(0xffffffffu, sum1, 2);

        float a0 = __expf(m0 - mn0), a1 = __expf(m1 - mn1);
        l0 = l0 * a0 + sum0; m0 = mn0;
        l1 = l1 * a1 + sum1; m1 = mn1;
#pragma unroll
        for (int nt = 0; nt < 8; nt++) {
            o[nt][0] *= a0; o[nt][1] *= a0;
            o[nt][2] *= a1; o[nt][3] *= a1;
        }

        // ---- O += P @ V ----
#pragma unroll
        for (int ks = 0; ks < 4; ks++) {
            uint4 AH;
            AH.x = pack_f16(s[2 * ks][0],     s[2 * ks][1]);
            AH.y = pack_f16(s[2 * ks][2],     s[2 * ks][3]);
            AH.z = pack_f16(s[2 * ks + 1][0], s[2 * ks + 1][1]);
            AH.w = pack_f16(s[2 * ks + 1][2], s[2 * ks + 1][3]);
            uint2 BH[8];
#pragma unroll
            for (int nt = 0; nt < 8; nt++)
                BH[nt] = *(const uint2*)&Vst[((ks * 8 + nt) * 32 + lane) * 2];
#pragma unroll
            for (int nt = 0; nt < 8; nt++) mma16(o[nt], AH, BH[nt]);
        }

        scur = snxt;
        snxt = (snxt == 2) ? 0 : snxt + 1;
    }

    // ---- normalize & write att16 in A-frag layout ----
    const float inv0 = 1.0f / l0, inv1 = 1.0f / l1;
    const int rowblk = (b * 2048 + qt * 64 + wid * 16) >> 7;
    const int mtl = (qt * 4 + wid) & 7;
#pragma unroll
    for (int ntp = 0; ntp < 4; ntp++) {
        const int nt0 = ntp * 2;
        uint4 w;
        w.x = pack_f16(o[nt0][0] * inv0,     o[nt0][1] * inv0);
        w.y = pack_f16(o[nt0][2] * inv1,     o[nt0][3] * inv1);
        w.z = pack_f16(o[nt0 + 1][0] * inv0, o[nt0 + 1][1] * inv0);
        w.w = pack_f16(o[nt0 + 1][2] * inv1, o[nt0 + 1][3] * inv1);
        const int chunk = h * 2 + (nt0 >> 2);
        const int ksx = (nt0 >> 1) & 1;
        size_t idx = ((((size_t)rowblk * 32 + chunk) * 2 + ksx) * 8 + mtl) * 32 + lane;
        *(uint4*)(att16 + idx * 4) = w;
    }
}

// ---------------------------------------------------------------------------
extern "C" void kernel_launch(void* const* d_in, const int* in_sizes, int n_in,
                              void* d_out, int out_size)
{
    const float* x      = (const float*)d_in[0];
    const float* w_qkv  = (const float*)d_in[1];
    const float* b_qkv  = (const float*)d_in[2];
    const float* w_proj = (const float*)d_in[3];
    const float* b_proj = (const float*)d_in[4];
    float* out = (float*)d_out;

    float* qkv = nullptr;
    uint32_t *x16, *wqkv16, *wproj16, *q16, *k16, *v16, *att16;
    cudaGetSymbolAddress((void**)&qkv, g_qkv);
    cudaGetSymbolAddress((void**)&x16, g_x16);
    cudaGetSymbolAddress((void**)&wqkv16, g_wqkv16);
    cudaGetSymbolAddress((void**)&wproj16, g_wproj16);
    cudaGetSymbolAddress((void**)&q16, g_q16);
    cudaGetSymbolAddress((void**)&k16, g_k16);
    cudaGetSymbolAddress((void**)&v16, g_v16);
    cudaGetSymbolAddress((void**)&att16, g_att16);

    cudaFuncSetAttribute(flash_mma,
                         cudaFuncAttributeMaxDynamicSharedMemorySize, FLASH_SMEM);
    cudaFuncSetAttribute(tc_gemm,
                         cudaFuncAttributeMaxDynamicSharedMemorySize, GEMM_SMEM);

    // 0) pack inputs/weights to fp16 fragment layouts
    pack_a<<<8192, 256>>>(x, x16);
    pack_w<<<6144, 256>>>(w_qkv, wqkv16, 3 * D_MODEL);
    pack_w<<<2048, 256>>>(w_proj, wproj16, D_MODEL);

    // 1) QKV GEMM: [4096,1024] @ [1024,3072] -> qkv fp32
    tc_gemm<<<dim3(24, 32), 256, GEMM_SMEM>>>(x16, wqkv16, b_qkv, qkv, 3 * D_MODEL);

    // 2) repack qkv to fp16 fragment layouts for attention
    repack_qkv<<<dim3(32, 16, 2), 128>>>(qkv, q16, k16, v16);

    // 3) causal flash attention -> att16 (A-frag fp16)
    flash_mma<<<dim3(32, 16, 2), 128, FLASH_SMEM>>>(q16, k16, v16, att16);

    // 4) output projection: [4096,1024] @ [1024,1024] -> out fp32
    tc_gemm<<<dim3(8, 32), 256, GEMM_SMEM>>>(att16, wproj16, b_proj, out, D_MODEL);
}

// round 11
// speedup vs baseline: 7.6364x; 1.0749x over previous
#include <cuda_runtime.h>
#include <cuda_fp16.h>
#include <cstdint>

#define D_MODEL 1024
#define N_HEADS 16
#define HEAD_DIM 64
#define SEQ 2048
#define BATCH 2
#define GK 1024

// Scratch (allocation-free rule: __device__ globals)
__device__ uint32_t g_x16[2097152];     // x packed, A-frag
__device__ uint32_t g_wqkv16[1572864];  // W_qkv^T packed, B-frag
__device__ uint32_t g_wproj16[524288];  // W_proj^T packed, B-frag
__device__ uint32_t g_q16[2097152];     // per (b,h,qt): [4ks][4mt][lane][4]
__device__ uint32_t g_k16[2097152];     // per (b,h,kt): [4ks][8nt][lane][2]
__device__ uint32_t g_v16[2097152];     // per (b,h,kt): [4ks][8nt][lane][2]
__device__ uint32_t g_att16[2097152];   // attention out, A-frag (proj input)

__device__ __forceinline__ uint32_t pack_f16(float x, float y) {
    __half2 p = __floats2half2_rn(x, y);
    return *reinterpret_cast<uint32_t*>(&p);
}

__device__ __forceinline__ void mma16(float* d, const uint4& a, const uint2& b) {
    asm volatile(
        "mma.sync.aligned.m16n8k16.row.col.f32.f16.f16.f32 "
        "{%0,%1,%2,%3}, {%4,%5,%6,%7}, {%8,%9}, {%0,%1,%2,%3};"
        : "+f"(d[0]), "+f"(d[1]), "+f"(d[2]), "+f"(d[3])
        : "r"(a.x), "r"(a.y), "r"(a.z), "r"(a.w), "r"(b.x), "r"(b.y));
}

__device__ __forceinline__ void cp16(uint32_t dst, const void* src) {
    asm volatile("cp.async.cg.shared.global [%0], [%1], 16;"
                 :: "r"(dst), "l"(src) : "memory");
}
#define CP_COMMIT() asm volatile("cp.async.commit_group;" ::: "memory")
#define CP_WAIT1()  asm volatile("cp.async.wait_group 1;" ::: "memory")
#define CP_WAIT0()  asm volatile("cp.async.wait_group 0;" ::: "memory")

// ---------------------------------------------------------------------------
// pack_a: fp32 [M,1024] row-major -> A-frag fp16 u32 layout
// ---------------------------------------------------------------------------
__global__ __launch_bounds__(256) void pack_a(const float* __restrict__ A,
                                              uint32_t* __restrict__ out) {
    int id = blockIdx.x * 256 + threadIdx.x;
    int f = id & 2047;
    int j = f & 3, lane = (f >> 2) & 31, mt = (f >> 7) & 7, ks = f >> 10;
    int chunk = (id >> 11) & 31;
    int rowblk = id >> 16;
    int r = rowblk * 128 + mt * 16 + (lane >> 2) + (j & 1) * 8;
    int k0 = chunk * 32 + ks * 16 + (lane & 3) * 2 + (j >> 1) * 8;
    float2 v = *(const float2*)(A + (size_t)r * GK + k0);
    out[id] = pack_f16(v.x, v.y);
}

// ---------------------------------------------------------------------------
// pack_w: fp32 W [1024, N] row-major -> B-frag fp16 u32 layout
// ---------------------------------------------------------------------------
__global__ __launch_bounds__(256) void pack_w(const float* __restrict__ W,
                                              uint32_t* __restrict__ out, int N) {
    int id = blockIdx.x * 256 + threadIdx.x;
    int f = id & 2047;
    int j = f & 1, lane = (f >> 1) & 31, nt = (f >> 6) & 15, ks = f >> 10;
    int chunk = (id >> 11) & 31;
    int colblk = id >> 16;
    int n = colblk * 128 + nt * 8 + (lane >> 2);
    int k0 = chunk * 32 + ks * 16 + (lane & 3) * 2 + j * 8;
    out[id] = pack_f16(W[(size_t)k0 * N + n], W[(size_t)(k0 + 1) * N + n]);
}

// ---------------------------------------------------------------------------
// shared GEMM mainloop: 128x128 CTA, K=1024, chunk 32, cp.async 3-stage.
// ---------------------------------------------------------------------------
__device__ __forceinline__ void gemm_mainloop(
    const uint32_t* __restrict__ Ab, const uint32_t* __restrict__ Bb,
    uint32_t* smu, float acc[4][4][4], int tid, int lane, int wm, int wn)
{
    const uint32_t smaddr = (uint32_t)__cvta_generic_to_shared(smu);

    auto cp_chunk = [&](int c, int s) {
        uint32_t d = smaddr + s * 16384 + tid * 16;
        const char* sa = (const char*)(Ab + c * 2048) + tid * 16;
        const char* sb = (const char*)(Bb + c * 2048) + tid * 16;
        cp16(d, sa);
        cp16(d + 4096, sa + 4096);
        cp16(d + 8192, sb);
        cp16(d + 12288, sb + 4096);
    };

    cp_chunk(0, 0);
    CP_COMMIT();

    for (int c = 0; c < 32; c++) {
        if (c < 31) {
            cp_chunk(c + 1, (c + 1) % 3);
            CP_COMMIT();
            CP_WAIT1();
        } else {
            CP_WAIT0();
        }
        __syncthreads();

        const uint32_t* base = smu + (c % 3) * 4096;
#pragma unroll
        for (int ks = 0; ks < 2; ks++) {
            uint4 AH[4];
            uint2 BH[4];
#pragma unroll
            for (int mi = 0; mi < 4; mi++)
                AH[mi] = *(const uint4*)&base[((ks * 8 + wm * 4 + mi) * 32 + lane) * 4];
#pragma unroll
            for (int ni = 0; ni < 4; ni++)
                BH[ni] = *(const uint2*)&base[2048 + ((ks * 16 + wn * 4 + ni) * 32 + lane) * 2];
#pragma unroll
            for (int mi = 0; mi < 4; mi++)
#pragma unroll
                for (int ni = 0; ni < 4; ni++)
                    mma16(acc[mi][ni], AH[mi], BH[ni]);
        }
    }
}

// ---------------------------------------------------------------------------
// tc_gemm_qkv: QKV GEMM with fused repack epilogue.
// Writes q16 (A-frag, pre-scaled 1/8), k16 (B-frag) directly from C-frags
// (lane-identical mapping); V via smem transpose restage.
// ---------------------------------------------------------------------------
#define GEMM_SMEM (3 * 16384)

__global__ __launch_bounds__(256, 2)
void tc_gemm_qkv(const uint32_t* __restrict__ A16, const uint32_t* __restrict__ B16,
                 const float* __restrict__ bias,
                 uint32_t* __restrict__ q16, uint32_t* __restrict__ k16,
                 uint32_t* __restrict__ v16)
{
    extern __shared__ uint32_t smu[];
    const int tid = threadIdx.x;
    const int lane = tid & 31;
    const int wid = tid >> 5;
    const int wm = wid >> 2;
    const int wn = wid & 3;
    const int row0 = blockIdx.y * 128;
    const int col0 = blockIdx.x * 128;

    float acc[4][4][4];
#pragma unroll
    for (int i = 0; i < 4; i++)
#pragma unroll
        for (int j = 0; j < 4; j++)
#pragma unroll
            for (int c = 0; c < 4; c++) acc[i][j][c] = 0.0f;

    gemm_mainloop(A16 + (size_t)blockIdx.y * 65536,
                  B16 + (size_t)blockIdx.x * 65536,
                  smu, acc, tid, lane, wm, wn);

    // add bias
#pragma unroll
    for (int ni = 0; ni < 4; ni++) {
        const int n = col0 + wn * 32 + ni * 8 + (lane & 3) * 2;
        float2 bb = *(const float2*)(bias + n);
#pragma unroll
        for (int mi = 0; mi < 4; mi++) {
            acc[mi][ni][0] += bb.x; acc[mi][ni][1] += bb.y;
            acc[mi][ni][2] += bb.x; acc[mi][ni][3] += bb.y;
        }
    }

    const int type = col0 >> 10;                 // 0=Q 1=K 2=V
    const int m0 = row0 + wm * 64 + (lane >> 2); // token of mi=0, c0/c1
    const int b = m0 >> 11;
    const int tile = (m0 & 2047) >> 6;           // qt / kt
    const int h = ((col0 & 1023) >> 6) + (wn >> 1);
    const size_t dbase = (((size_t)(b * 16 + h)) * 32 + tile) * 2048;

    if (type == 0) {
        // Q: A-frag direct store, scaled 1/8
        uint32_t* dst = q16 + dbase;
#pragma unroll
        for (int mi = 0; mi < 4; mi++)
#pragma unroll
            for (int ni = 0; ni < 4; ni++) {
                int ks = (wn & 1) * 2 + (ni >> 1);
                int f = ks * 512 + mi * 128 + lane * 4 + (ni & 1) * 2;
                uint2 w;
                w.x = pack_f16(acc[mi][ni][0] * 0.125f, acc[mi][ni][1] * 0.125f);
                w.y = pack_f16(acc[mi][ni][2] * 0.125f, acc[mi][ni][3] * 0.125f);
                *(uint2*)(dst + f) = w;
            }
    } else if (type == 1) {
        // K: B-frag direct store
        uint32_t* dst = k16 + dbase;
#pragma unroll
        for (int mi = 0; mi < 4; mi++)
#pragma unroll
            for (int p = 0; p < 2; p++) {       // ni pair (2p, 2p+1)
                int ks = (wn & 1) * 2 + p;
                uint2 w0, w1;                    // nt = 2mi (c0c1), 2mi+1 (c2c3)
                w0.x = pack_f16(acc[mi][2 * p][0],     acc[mi][2 * p][1]);
                w0.y = pack_f16(acc[mi][2 * p + 1][0], acc[mi][2 * p + 1][1]);
                w1.x = pack_f16(acc[mi][2 * p][2],     acc[mi][2 * p][3]);
                w1.y = pack_f16(acc[mi][2 * p + 1][2], acc[mi][2 * p + 1][3]);
                *(uint2*)(dst + ks * 512 + (mi * 2) * 64 + lane * 2) = w0;
                *(uint2*)(dst + ks * 512 + (mi * 2 + 1) * 64 + lane * 2) = w1;
            }
    } else {
        // V: restage through smem [128 tokens][136 halfs] then B-frag out
        __syncthreads();
        __half* sh = (__half*)smu;
#pragma unroll
        for (int mi = 0; mi < 4; mi++) {
            int rl = wm * 64 + mi * 16 + (lane >> 2);
#pragma unroll
            for (int ni = 0; ni < 4; ni++) {
                int cl = wn * 32 + ni * 8 + (lane & 3) * 2;
                *(__half2*)&sh[rl * 136 + cl] =
                    __floats2half2_rn(acc[mi][ni][0], acc[mi][ni][1]);
                *(__half2*)&sh[(rl + 8) * 136 + cl] =
                    __floats2half2_rn(acc[mi][ni][2], acc[mi][ni][3]);
            }
        }
        __syncthreads();

        const int h0 = (col0 & 1023) >> 6;
        const int kt0 = (row0 & 2047) >> 6;
        const int bb2 = row0 >> 11;
#pragma unroll
        for (int g = 0; g < 4; g++) {           // (hi, kt_l)
            int hi = g >> 1, kt_l = g & 1;
            uint32_t* dst = v16 +
                ((((size_t)(bb2 * 16 + h0 + hi)) * 32) + kt0 + kt_l) * 2048;
#pragma unroll
            for (int i = 0; i < 8; i++) {
                int f = tid + i * 256;
                int j = f & 1, ln = (f >> 1) & 31, nt = (f >> 6) & 7, ks = f >> 9;
                int kv = kt_l * 64 + ks * 16 + (ln & 3) * 2 + j * 8;
                int d = hi * 64 + nt * 8 + (ln >> 2);
                dst[f] = pack_f16(__half2float(sh[kv * 136 + d]),
                                  __half2float(sh[(kv + 1) * 136 + d]));
            }
        }
    }
}

// ---------------------------------------------------------------------------
// tc_gemm: generic fp32-out GEMM + bias (proj). Same mainloop.
// ---------------------------------------------------------------------------
__global__ __launch_bounds__(256, 2)
void tc_gemm(const uint32_t* __restrict__ A16, const uint32_t* __restrict__ B16,
             const float* __restrict__ bias, float* __restrict__ C, int N)
{
    extern __shared__ uint32_t smu[];
    const int tid = threadIdx.x;
    const int lane = tid & 31;
    const int wid = tid >> 5;
    const int wm = wid >> 2;
    const int wn = wid & 3;
    const int row0 = blockIdx.y * 128;
    const int col0 = blockIdx.x * 128;

    float acc[4][4][4];
#pragma unroll
    for (int i = 0; i < 4; i++)
#pragma unroll
        for (int j = 0; j < 4; j++)
#pragma unroll
            for (int c = 0; c < 4; c++) acc[i][j][c] = 0.0f;

    gemm_mainloop(A16 + (size_t)blockIdx.y * 65536,
                  B16 + (size_t)blockIdx.x * 65536,
                  smu, acc, tid, lane, wm, wn);

#pragma unroll
    for (int mi = 0; mi < 4; mi++) {
        const int m = row0 + wm * 64 + mi * 16 + (lane >> 2);
#pragma unroll
        for (int ni = 0; ni < 4; ni++) {
            const int n = col0 + wn * 32 + ni * 8 + (lane & 3) * 2;
            float2 bb = *(const float2*)(bias + n);
            float2 o0 = make_float2(acc[mi][ni][0] + bb.x, acc[mi][ni][1] + bb.y);
            float2 o1 = make_float2(acc[mi][ni][2] + bb.x, acc[mi][ni][3] + bb.y);
            *(float2*)(C + (size_t)m * N + n) = o0;
            *(float2*)(C + (size_t)(m + 8) * N + n) = o1;
        }
    }
}

// ---------------------------------------------------------------------------
// flash_mma: Q in registers, K/V via cp.async 3-stage, att16 out (A-frag).
// ---------------------------------------------------------------------------
#define FLASH_SMEM (3 * 16384)

__global__ __launch_bounds__(128, 4) void flash_mma(
    const uint32_t* __restrict__ q16, const uint32_t* __restrict__ k16,
    const uint32_t* __restrict__ v16, uint32_t* __restrict__ att16)
{
    extern __shared__ uint32_t su[];
    const int tid = threadIdx.x;
    const int lane = tid & 31;
    const int wid = tid >> 5;
    const int qt = gridDim.x - 1 - blockIdx.x;   // heavy blocks first
    const int h  = blockIdx.y;
    const int b  = blockIdx.z;

    const size_t bh = ((size_t)(b * 16 + h)) * 32;
    const uint32_t* kg = k16 + bh * 2048;
    const uint32_t* vg = v16 + bh * 2048;
    const uint32_t* qg = q16 + (bh + qt) * 2048;
    const uint32_t smaddr = (uint32_t)__cvta_generic_to_shared(su);

    uint4 QR[4];
#pragma unroll
    for (int ks = 0; ks < 4; ks++)
        QR[ks] = *(const uint4*)(qg + ((ks * 4 + wid) * 32 + lane) * 4);

    auto cp_tile = [&](int kt, int s) {
        uint32_t d = smaddr + s * 16384 + tid * 16;
        const char* sk = (const char*)(kg + kt * 2048) + tid * 16;
        const char* sv = (const char*)(vg + kt * 2048) + tid * 16;
#pragma unroll
        for (int r = 0; r < 4; r++) cp16(d + r * 2048, sk + r * 2048);
#pragma unroll
        for (int r = 0; r < 4; r++) cp16(d + 8192 + r * 2048, sv + r * 2048);
    };

    float o[8][4];
#pragma unroll
    for (int nt = 0; nt < 8; nt++)
#pragma unroll
        for (int c = 0; c < 4; c++) o[nt][c] = 0.0f;
    float m0 = -1e30f, m1 = -1e30f, l0 = 0.0f, l1 = 0.0f;

    const int rq0 = qt * 64 + wid * 16 + (lane >> 2);

    cp_tile(0, 0);
    CP_COMMIT();

    int scur = 0, snxt = 1;
    for (int t = 0; t <= qt; t++) {
        if (t < qt) {
            cp_tile(t + 1, snxt);
            CP_COMMIT();
            CP_WAIT1();
        } else {
            CP_WAIT0();
        }
        __syncthreads();

        const uint32_t* Kst = su + scur * 4096;
        const uint32_t* Vst = Kst + 2048;

        float s[8][4];
#pragma unroll
        for (int nt = 0; nt < 8; nt++)
#pragma unroll
            for (int c = 0; c < 4; c++) s[nt][c] = 0.0f;

#pragma unroll
        for (int ks = 0; ks < 4; ks++) {
            uint2 BH[8];
#pragma unroll
            for (int nt = 0; nt < 8; nt++)
                BH[nt] = *(const uint2*)&Kst[((ks * 8 + nt) * 32 + lane) * 2];
#pragma unroll
            for (int nt = 0; nt < 8; nt++) mma16(s[nt], QR[ks], BH[nt]);
        }

        if (t == qt) {
            const int k0 = t * 64;
#pragma unroll
            for (int nt = 0; nt < 8; nt++) {
                int c = k0 + nt * 8 + (lane & 3) * 2;
                if (c > rq0)         s[nt][0] = -1e30f;
                if (c + 1 > rq0)     s[nt][1] = -1e30f;
                if (c > rq0 + 8)     s[nt][2] = -1e30f;
                if (c + 1 > rq0 + 8) s[nt][3] = -1e30f;
            }
        }

        float mx0 = -1e30f, mx1 = -1e30f;
#pragma unroll
        for (int nt = 0; nt < 8; nt++) {
            mx0 = fmaxf(mx0, fmaxf(s[nt][0], s[nt][1]));
            mx1 = fmaxf(mx1, fmaxf(s[nt][2], s[nt][3]));
        }
        mx0 = fmaxf(mx0, __shfl_xor_sync(0xffffffffu, mx0, 1));
        mx0 = fmaxf(mx0, __shfl_xor_sync(0xffffffffu, mx0, 2));
        mx1 = fmaxf(mx1, __shfl_xor_sync(0xffffffffu, mx1, 1));
        mx1 = fmaxf(mx1, __shfl_xor_sync(0xffffffffu, mx1, 2));
        float mn0 = fmaxf(m0, mx0), mn1 = fmaxf(m1, mx1);

        float sum0 = 0.0f, sum1 = 0.0f;
#pragma unroll
        for (int nt = 0; nt < 8; nt++) {
            s[nt][0] = __expf(s[nt][0] - mn0);
            s[nt][1] = __expf(s[nt][1] - mn0);
            s[nt][2] = __expf(s[nt][2] - mn1);
            s[nt][3] = __expf(s[nt][3] - mn1);
            sum0 += s[nt][0] + s[nt][1];
            sum1 += s[nt][2] + s[nt][3];
        }
        sum0 += __shfl_xor_sync(0xffffffffu, sum0, 1);
        sum0 += __shfl_xor_sync(0xffffffffu, sum0, 2);
        sum1 += __shfl_xor_sync(0xffffffffu, sum1, 1);
        sum1 += __shfl_xor_sync(0xffffffffu, sum1, 2);

        float a0 = __expf(m0 - mn0), a1 = __expf(m1 - mn1);
        l0 = l0 * a0 + sum0; m0 = mn0;
        l1 = l1 * a1 + sum1; m1 = mn1;
#pragma unroll
        for (int nt = 0; nt < 8; nt++) {
            o[nt][0] *= a0; o[nt][1] *= a0;
            o[nt][2] *= a1; o[nt][3] *= a1;
        }

#pragma unroll
        for (int ks = 0; ks < 4; ks++) {
            uint4 AH;
            AH.x = pack_f16(s[2 * ks][0],     s[2 * ks][1]);
            AH.y = pack_f16(s[2 * ks][2],     s[2 * ks][3]);
            AH.z = pack_f16(s[2 * ks + 1][0], s[2 * ks + 1][1]);
            AH.w = pack_f16(s[2 * ks + 1][2], s[2 * ks + 1][3]);
            uint2 BH[8];
#pragma unroll
            for (int nt = 0; nt < 8; nt++)
                BH[nt] = *(const uint2*)&Vst[((ks * 8 + nt) * 32 + lane) * 2];
#pragma unroll
            for (int nt = 0; nt < 8; nt++) mma16(o[nt], AH, BH[nt]);
        }

        scur = snxt;
        snxt = (snxt == 2) ? 0 : snxt + 1;
    }

    const float inv0 = 1.0f / l0, inv1 = 1.0f / l1;
    const int rowblk = (b * 2048 + qt * 64 + wid * 16) >> 7;
    const int mtl = (qt * 4 + wid) & 7;
#pragma unroll
    for (int ntp = 0; ntp < 4; ntp++) {
        const int nt0 = ntp * 2;
        uint4 w;
        w.x = pack_f16(o[nt0][0] * inv0,     o[nt0][1] * inv0);
        w.y = pack_f16(o[nt0][2] * inv1,     o[nt0][3] * inv1);
        w.z = pack_f16(o[nt0 + 1][0] * inv0, o[nt0 + 1][1] * inv0);
        w.w = pack_f16(o[nt0 + 1][2] * inv1, o[nt0 + 1][3] * inv1);
        const int chunk = h * 2 + (nt0 >> 2);
        const int ksx = (nt0 >> 1) & 1;
        size_t idx = ((((size_t)rowblk * 32 + chunk) * 2 + ksx) * 8 + mtl) * 32 + lane;
        *(uint4*)(att16 + idx * 4) = w;
    }
}

// ---------------------------------------------------------------------------
extern "C" void kernel_launch(void* const* d_in, const int* in_sizes, int n_in,
                              void* d_out, int out_size)
{
    const float* x      = (const float*)d_in[0];
    const float* w_qkv  = (const float*)d_in[1];
    const float* b_qkv  = (const float*)d_in[2];
    const float* w_proj = (const float*)d_in[3];
    const float* b_proj = (const float*)d_in[4];
    float* out = (float*)d_out;

    uint32_t *x16, *wqkv16, *wproj16, *q16, *k16, *v16, *att16;
    cudaGetSymbolAddress((void**)&x16, g_x16);
    cudaGetSymbolAddress((void**)&wqkv16, g_wqkv16);
    cudaGetSymbolAddress((void**)&wproj16, g_wproj16);
    cudaGetSymbolAddress((void**)&q16, g_q16);
    cudaGetSymbolAddress((void**)&k16, g_k16);
    cudaGetSymbolAddress((void**)&v16, g_v16);
    cudaGetSymbolAddress((void**)&att16, g_att16);

    cudaFuncSetAttribute(flash_mma,
                         cudaFuncAttributeMaxDynamicSharedMemorySize, FLASH_SMEM);
    cudaFuncSetAttribute(tc_gemm,
                         cudaFuncAttributeMaxDynamicSharedMemorySize, GEMM_SMEM);
    cudaFuncSetAttribute(tc_gemm_qkv,
                         cudaFuncAttributeMaxDynamicSharedMemorySize, GEMM_SMEM);

    // 0) pack inputs/weights to fp16 fragment layouts
    pack_a<<<8192, 256>>>(x, x16);
    pack_w<<<6144, 256>>>(w_qkv, wqkv16, 3 * D_MODEL);
    pack_w<<<2048, 256>>>(w_proj, wproj16, D_MODEL);

    // 1) QKV GEMM with fused repack epilogue -> q16/k16/v16
    tc_gemm_qkv<<<dim3(24, 32), 256, GEMM_SMEM>>>(
        x16, wqkv16, b_qkv, q16, k16, v16);

    // 2) causal flash attention -> att16 (A-frag fp16)
    flash_mma<<<dim3(32, 16, 2), 128, FLASH_SMEM>>>(q16, k16, v16, att16);

    // 3) output projection: [4096,1024] @ [1024,1024] -> out fp32
    tc_gemm<<<dim3(8, 32), 256, GEMM_SMEM>>>(att16, wproj16, b_proj, out, D_MODEL);
}